// round 5
// baseline (speedup 1.0000x reference)
#include <cuda_runtime.h>
#include <cuda_bf16.h>
#include <math.h>
#include <stdint.h>

#define NMAX 65536
#define SA 136               // tile stride in halves
#define P_STRIDE 66
#define BHALF (64 * SA)      // halves per split per dim-tile
#define BBUF (2 * BHALF)     // hi+lo halves per dim  (34816 bytes)
#define BBUF_BYTES (BBUF * 2)
#define ALO_BYTES (128 * SA * 2)   // offset of A-lo within staging

// h2 scratch as bf16 hi/lo splits, transposed: [f * N + row]
__device__ __nv_bfloat16 g_h2_hi[128 * NMAX];
__device__ __nv_bfloat16 g_h2_lo[128 * NMAX];
// Pre-split W2 tiles: per j (32), [hi: 64xSA][lo: 64xSA], n-major, zero-padded
__device__ __nv_bfloat16 g_w2s[32 * BBUF];
// Padded bias: [32][64]
__device__ float g_b2p[32 * 64];

__device__ __forceinline__ float swishf(float v) {
    return __fdividef(v, 1.0f + __expf(-v));
}

__device__ __forceinline__ void split_bf16(float v, __nv_bfloat16* h, __nv_bfloat16* l) {
    __nv_bfloat16 hh = __float2bfloat16(v);
    *h = hh;
    *l = __float2bfloat16(v - __bfloat162float(hh));
}

__device__ __forceinline__ void mma16816(float* c, const uint32_t* a,
                                         uint32_t b0, uint32_t b1) {
    asm volatile(
        "mma.sync.aligned.m16n8k16.row.col.f32.bf16.bf16.f32 "
        "{%0,%1,%2,%3}, {%4,%5,%6,%7}, {%8,%9}, {%0,%1,%2,%3};"
        : "+f"(c[0]), "+f"(c[1]), "+f"(c[2]), "+f"(c[3])
        : "r"(a[0]), "r"(a[1]), "r"(a[2]), "r"(a[3]), "r"(b0), "r"(b1));
}

#define LDSM4(d, addr)                                                       \
    asm volatile("ldmatrix.sync.aligned.m8n8.x4.shared.b16 {%0,%1,%2,%3}, [%4];" \
        : "=r"((d)[0]), "=r"((d)[1]), "=r"((d)[2]), "=r"((d)[3]) : "r"(addr))

__device__ __forceinline__ uint32_t smem_u32(const void* p) {
    uint32_t a;
    asm("{ .reg .u64 t; cvta.to.shared.u64 t, %1; cvt.u32.u64 %0, t; }" : "=r"(a) : "l"(p));
    return a;
}

// ---------------------------------------------------------------------------
// Prep: split W2 into bf16 hi/lo tiles (n-major, padded) + padded bias
// ---------------------------------------------------------------------------
__global__ __launch_bounds__(256)
void k_prep(const float* __restrict__ W2, const float* __restrict__ b2)
{
    int idx = blockIdx.x * 256 + threadIdx.x;
    if (idx < 32 * BHALF) {
        int j = idx / BHALF;
        int rem = idx - j * BHALF;
        int n = rem / SA;
        int k = rem - n * SA;
        float v = (n < 47 && k < 128) ? W2[(size_t)k * 1504 + j * 47 + n] : 0.0f;
        __nv_bfloat16 h, l;
        split_bf16(v, &h, &l);
        g_w2s[(size_t)j * BBUF + rem]          = h;
        g_w2s[(size_t)j * BBUF + BHALF + rem]  = l;
    }
    if (idx < 32 * 64) {
        int j = idx >> 6, cc = idx & 63;
        g_b2p[idx] = (cc < 47) ? b2[j * 47 + cc] : 0.0f;
    }
}

// ---------------------------------------------------------------------------
// Kernel 1: BN + Dense(48->128)+swish + Dense(128->128)+swish -> bf16 hi/lo
// ---------------------------------------------------------------------------
__global__ __launch_bounds__(256)
void k_mlp(const float* __restrict__ x, const float* __restrict__ c,
           const float* __restrict__ bn_scale, const float* __restrict__ bn_bias,
           const float* __restrict__ bn_mean, const float* __restrict__ bn_var,
           const float* __restrict__ W0, const float* __restrict__ b0,
           const float* __restrict__ W1, const float* __restrict__ b1,
           float* __restrict__ out, int N)
{
    extern __shared__ float sm[];
    float* W0s = sm;
    float* W1s = W0s + 48 * 128;
    float* b0s = W1s + 128 * 128;
    float* b1s = b0s + 128;
    float* ab  = b1s + 128;
    float* A0s = ab + 96;
    float* A1s = A0s + 48 * 65;
    float* A2s = A1s + 128 * 65;

    const int tid  = threadIdx.x;
    const int row0 = blockIdx.x * 64;

    for (int i = tid; i < 48 * 128; i += 256)  W0s[i] = W0[i];
    for (int i = tid; i < 128 * 128; i += 256) W1s[i] = W1[i];
    if (tid < 128) { b0s[tid] = b0[tid]; b1s[tid] = b1[tid]; }
    if (tid < 48) {
        float a = bn_scale[tid] * rsqrtf(bn_var[tid] + 1e-5f);
        ab[tid]      = a;
        ab[48 + tid] = bn_bias[tid] - bn_mean[tid] * a;
    }
    __syncthreads();

    for (int idx = tid; idx < 64 * 32; idx += 256) {
        int k = idx & 31, r = idx >> 5;
        float v = x[(size_t)(row0 + r) * 64 + 32 + k];
        out[(size_t)(row0 + r) * 64 + 32 + k] = v;
        A0s[k * 65 + r] = v * ab[k] + ab[48 + k];
    }
    for (int idx = tid; idx < 64 * 16; idx += 256) {
        int k = idx & 15, r = idx >> 4;
        float v = c[(size_t)(row0 + r) * 16 + k];
        int kk = 32 + k;
        A0s[kk * 65 + r] = v * ab[kk] + ab[48 + kk];
    }
    __syncthreads();

    const int rt = tid >> 4, ct = tid & 15;
    const int r0 = rt * 4, f0 = ct * 8;

    {
        float acc[4][8];
        #pragma unroll
        for (int i = 0; i < 4; i++)
            #pragma unroll
            for (int q = 0; q < 8; q++) acc[i][q] = 0.0f;
        #pragma unroll 4
        for (int k = 0; k < 48; k++) {
            float a0 = A0s[k * 65 + r0 + 0];
            float a1 = A0s[k * 65 + r0 + 1];
            float a2 = A0s[k * 65 + r0 + 2];
            float a3 = A0s[k * 65 + r0 + 3];
            float4 wA = *(const float4*)&W0s[k * 128 + f0];
            float4 wB = *(const float4*)&W0s[k * 128 + f0 + 4];
            float w[8] = {wA.x, wA.y, wA.z, wA.w, wB.x, wB.y, wB.z, wB.w};
            #pragma unroll
            for (int q = 0; q < 8; q++) {
                acc[0][q] += a0 * w[q]; acc[1][q] += a1 * w[q];
                acc[2][q] += a2 * w[q]; acc[3][q] += a3 * w[q];
            }
        }
        #pragma unroll
        for (int q = 0; q < 8; q++) {
            float bb = b0s[f0 + q];
            #pragma unroll
            for (int i = 0; i < 4; i++)
                A1s[(f0 + q) * 65 + (r0 + i)] = swishf(acc[i][q] + bb);
        }
    }
    __syncthreads();

    {
        float acc[4][8];
        #pragma unroll
        for (int i = 0; i < 4; i++)
            #pragma unroll
            for (int q = 0; q < 8; q++) acc[i][q] = 0.0f;
        #pragma unroll 4
        for (int k = 0; k < 128; k++) {
            float a0 = A1s[k * 65 + r0 + 0];
            float a1 = A1s[k * 65 + r0 + 1];
            float a2 = A1s[k * 65 + r0 + 2];
            float a3 = A1s[k * 65 + r0 + 3];
            float4 wA = *(const float4*)&W1s[k * 128 + f0];
            float4 wB = *(const float4*)&W1s[k * 128 + f0 + 4];
            float w[8] = {wA.x, wA.y, wA.z, wA.w, wB.x, wB.y, wB.z, wB.w};
            #pragma unroll
            for (int q = 0; q < 8; q++) {
                acc[0][q] += a0 * w[q]; acc[1][q] += a1 * w[q];
                acc[2][q] += a2 * w[q]; acc[3][q] += a3 * w[q];
            }
        }
        #pragma unroll
        for (int q = 0; q < 8; q++) {
            float bb = b1s[f0 + q];
            #pragma unroll
            for (int i = 0; i < 4; i++)
                A2s[(f0 + q) * 64 + (r0 + i)] = swishf(acc[i][q] + bb);
        }
    }
    __syncthreads();

    for (int idx = tid; idx < 128 * 64; idx += 256) {
        int f = idx >> 6, r = idx & 63;
        float v = A2s[idx];
        __nv_bfloat16 h, l;
        split_bf16(v, &h, &l);
        g_h2_hi[(size_t)f * N + row0 + r] = h;
        g_h2_lo[(size_t)f * N + row0 + r] = l;
    }
}

// ---------------------------------------------------------------------------
// Kernel 2: HMMA + ldmatrix + A-in-registers + warp-local spline.
// smem: region0 = union(A staging 69632B, P[128x66]+bias[32x64] = 41984B)
//       region1 = B double buffer 2 x 34816B
// ---------------------------------------------------------------------------
__global__ __launch_bounds__(256)
void k_spline_mma(const float* __restrict__ x, float* __restrict__ out, int N)
{
    extern __shared__ char smem[];
    // region0 (69632B): A staging during prologue, then P + bias
    __nv_bfloat16* AHs = (__nv_bfloat16*)smem;
    float* P    = (float*)smem;
    float* bias = P + 128 * P_STRIDE;
    // region1: B double buffer
    char* Bbase = smem + 69632;

    const int tid  = threadIdx.x;
    const int warp = tid >> 5;
    const int lane = tid & 31;
    const int g    = lane >> 2;
    const int c2   = lane & 3;
    const int r0   = warp * 16;
    const int row0 = blockIdx.x * 128;

    const uint32_t sb0 = smem_u32(smem);
    const uint32_t sbB = smem_u32(Bbase);

    // ---- Prefetch B(0) via cp.async (2176 x 16B chunks) -- into region1
    {
        const char* bsrc = (const char*)g_w2s;
        #pragma unroll
        for (int it = 0; it < 9; it++) {
            int ch = tid + it * 256;
            if (ch < 2176) {
                asm volatile("cp.async.cg.shared.global [%0], [%1], 16;"
                             :: "r"(sbB + ch * 16), "l"(bsrc + ch * 16) : "memory");
            }
        }
        asm volatile("cp.async.commit_group;" ::: "memory");
    }

    // ---- Stage A tile (h2 hi/lo) into region0, vectorized (4 halves/thread)
    for (int idx = tid; idx < 128 * 32; idx += 256) {
        int k = idx >> 5, r4 = (idx & 31) * 4;
        size_t gaddr = (size_t)k * N + row0 + r4;
        uint32_t so = (uint32_t)(r4 * SA + k) * 2;  // wrong layout? no: staging row-major [r][k]
        // store 4 rows at column k (rows r4..r4+3)
        __nv_bfloat16 h0 = g_h2_hi[gaddr + 0], h1 = g_h2_hi[gaddr + 1];
        __nv_bfloat16 h2 = g_h2_hi[gaddr + 2], h3 = g_h2_hi[gaddr + 3];
        AHs[(r4 + 0) * SA + k] = h0;
        AHs[(r4 + 1) * SA + k] = h1;
        AHs[(r4 + 2) * SA + k] = h2;
        AHs[(r4 + 3) * SA + k] = h3;
        __nv_bfloat16 l0 = g_h2_lo[gaddr + 0], l1 = g_h2_lo[gaddr + 1];
        __nv_bfloat16 l2 = g_h2_lo[gaddr + 2], l3 = g_h2_lo[gaddr + 3];
        __nv_bfloat16* ALs = AHs + 128 * SA;
        ALs[(r4 + 0) * SA + k] = l0;
        ALs[(r4 + 1) * SA + k] = l1;
        ALs[(r4 + 2) * SA + k] = l2;
        ALs[(r4 + 3) * SA + k] = l3;
        (void)so;
    }
    __syncthreads();

    // ---- LDSM all A fragments into registers (8 ks x hi/lo x 4 regs)
    uint32_t afh[8][4], afl[8][4];
    {
        uint32_t a_addr = sb0 + (uint32_t)(((r0 + (lane & 15)) * SA + ((lane >> 4) << 3)) * 2);
        #pragma unroll
        for (int ks = 0; ks < 8; ks++) {
            LDSM4(afh[ks], a_addr + ks * 32);
            LDSM4(afl[ks], a_addr + ks * 32 + ALO_BYTES);
        }
    }
    __syncthreads();   // A staging dead; region0 becomes P + bias

    // ---- Bias table (all 32 dims) into region0 tail
    for (int idx = tid; idx < 32 * 64; idx += 256)
        bias[idx] = g_b2p[idx];

    // Per-thread B ldmatrix offset components
    const uint32_t b_noff = (uint32_t)(((lane & 7) + ((lane >> 4) << 3)) * SA * 2);
    const uint32_t b_koff = (uint32_t)(((lane >> 3) & 1) << 4);

    float logdet = 0.0f;
    const int myrow = r0 + lane;           // spline row (lane < 16)
    const size_t grow = (size_t)(row0 + myrow);

    for (int j = 0; j < 32; j++) {
        asm volatile("cp.async.wait_group 0;" ::: "memory");
        __syncthreads();   // B(j) visible; bias visible (j==0); P(j-1) reads done

        // ---- Prefetch B(j+1)
        if (j + 1 < 32) {
            uint32_t bdst = sbB + ((j + 1) & 1) * BBUF_BYTES;
            const char* bsrc = (const char*)(g_w2s + (size_t)(j + 1) * BBUF);
            #pragma unroll
            for (int it = 0; it < 9; it++) {
                int ch = tid + it * 256;
                if (ch < 2176) {
                    asm volatile("cp.async.cg.shared.global [%0], [%1], 16;"
                                 :: "r"(bdst + ch * 16), "l"(bsrc + ch * 16) : "memory");
                }
            }
        }
        asm volatile("cp.async.commit_group;" ::: "memory");

        // ---- GEMM: 16 rows x 64 cols, 3 split terms, fragments via ldmatrix
        const uint32_t bh_base = sbB + (j & 1) * BBUF_BYTES + b_noff + b_koff;
        const uint32_t bl_base = bh_base + BHALF * 2;

        float acc[8][4];
        #pragma unroll
        for (int t = 0; t < 8; t++)
            #pragma unroll
            for (int q = 0; q < 4; q++) acc[t][q] = 0.0f;

        #pragma unroll
        for (int ks = 0; ks < 8; ks++) {
            uint32_t bh[4][4], bl[4][4];
            #pragma unroll
            for (int t2 = 0; t2 < 4; t2++) {
                uint32_t o = (uint32_t)(t2 * 16 * SA * 2 + ks * 32);
                LDSM4(bh[t2], bh_base + o);
                LDSM4(bl[t2], bl_base + o);
            }
            #pragma unroll
            for (int t2 = 0; t2 < 4; t2++) {
                mma16816(acc[2 * t2],     afh[ks], bh[t2][0], bh[t2][1]);  // hi*hi
                mma16816(acc[2 * t2],     afl[ks], bh[t2][0], bh[t2][1]);  // lo*hi
                mma16816(acc[2 * t2],     afh[ks], bl[t2][0], bl[t2][1]);  // hi*lo
                mma16816(acc[2 * t2 + 1], afh[ks], bh[t2][2], bh[t2][3]);
                mma16816(acc[2 * t2 + 1], afl[ks], bh[t2][2], bh[t2][3]);
                mma16816(acc[2 * t2 + 1], afh[ks], bl[t2][2], bl[t2][3]);
            }
        }

        // ---- Epilogue: bias, exp for softmax cols (<32), warp-private P
        const float* bj = &bias[j * 64];
        #pragma unroll
        for (int t = 0; t < 8; t++) {
            int cb = 8 * t + 2 * c2;
            float2 bb = *(const float2*)&bj[cb];
            float v00 = acc[t][0] + bb.x, v01 = acc[t][1] + bb.y;
            float v10 = acc[t][2] + bb.x, v11 = acc[t][3] + bb.y;
            if (t < 4) {
                v00 = __expf(v00); v01 = __expf(v01);
                v10 = __expf(v10); v11 = __expf(v11);
            }
            *(float2*)&P[(r0 + g) * P_STRIDE + cb]     = make_float2(v00, v01);
            *(float2*)&P[(r0 + g + 8) * P_STRIDE + cb] = make_float2(v10, v11);
        }
        __syncwarp();

        // ---- Spline: warp-local, lanes 0..15 (one per row)
        if (lane < 16) {
            const float* pr = &P[myrow * P_STRIDE];
            float tin = __ldg(&x[grow * 64 + j]);

            float sW = 0.0f, sH = 0.0f;
            #pragma unroll
            for (int i = 0; i < 16; i++) { sW += pr[i]; sH += pr[16 + i]; }
            float invW = __fdividef(1.0f, sW);
            float invH = __fdividef(1.0f, sH);

            float tc  = fminf(fmaxf(tin, 0.0f), 1.0f);
            bool  inb = (tin >= 0.0f) && (tin <= 1.0f);

            float xk = 0.0f, cy = 0.0f;
            float xk_b = 0.0f, yk_b = 0.0f;
            float dx_b = pr[0] * invW, dy_b = pr[16] * invH;
            int bidx = 0;
            #pragma unroll
            for (int i = 0; i < 16; i++) {
                float dxi = pr[i] * invW;
                float dyi = pr[16 + i] * invH;
                if (xk <= tc) { bidx = i; xk_b = xk; dx_b = dxi; yk_b = cy; dy_b = dyi; }
                xk += dxi; cy += dyi;
            }

            float v0 = pr[32 + ((bidx > 0) ? bidx - 1 : 0)];
            float v1 = pr[32 + ((bidx < 15) ? bidx : 14)];
            float sp0 = fmaxf(v0, 0.0f) + __logf(1.0f + __expf(-fabsf(v0)));
            float sp1 = fmaxf(v1, 0.0f) + __logf(1.0f + __expf(-fabsf(v1)));
            float d0 = (bidx == 0)  ? 1.0f : sp0;
            float d1 = (bidx == 15) ? 1.0f : sp1;

            float xi   = __fdividef(tc - xk_b, dx_b);
            float s    = __fdividef(dy_b, dx_b);
            float xi1m = xi * (1.0f - xi);
            float den  = s + (d0 + d1 - 2.0f * s) * xi1m;
            float num  = s * xi * xi + d0 * xi1m;
            float y_in = yk_b + dy_b * __fdividef(num, den);
            float omxi = 1.0f - xi;
            float dnum = d1 * xi * xi + 2.0f * s * xi1m + d0 * omxi * omxi;
            float dydx = __fdividef(s * s * dnum, den * den);

            out[grow * 64 + j] = inb ? y_in : tin;
            logdet += inb ? __logf(dydx) : 0.0f;
        }
        __syncwarp();
    }

    if (lane < 16)
        out[(size_t)N * 64 + row0 + myrow] = logdet;
}

// ---------------------------------------------------------------------------
extern "C" void kernel_launch(void* const* d_in, const int* in_sizes, int n_in,
                              void* d_out, int out_size)
{
    const float* x  = (const float*)d_in[0];
    const float* c  = (const float*)d_in[1];
    const float* bs = (const float*)d_in[2];
    const float* bb = (const float*)d_in[3];
    const float* bm = (const float*)d_in[4];
    const float* bv = (const float*)d_in[5];
    const float* W0 = (const float*)d_in[6];
    const float* b0 = (const float*)d_in[7];
    const float* W1 = (const float*)d_in[8];
    const float* b1 = (const float*)d_in[9];
    const float* W2 = (const float*)d_in[10];
    const float* b2 = (const float*)d_in[11];
    float* out = (float*)d_out;

    int N = in_sizes[0] / 64;

    size_t sm1 = (size_t)(48*128 + 128*128 + 128 + 128 + 96 + 48*65 + 128*65 + 128*64) * sizeof(float);
    size_t sm2 = 69632 + 2 * BBUF_BYTES;   // region0 + B double buffer = 139264

    cudaFuncSetAttribute(k_mlp,        cudaFuncAttributeMaxDynamicSharedMemorySize, (int)sm1);
    cudaFuncSetAttribute(k_spline_mma, cudaFuncAttributeMaxDynamicSharedMemorySize, (int)sm2);

    k_prep<<<(32 * BHALF + 255) / 256, 256>>>(W2, b2);
    k_mlp<<<N / 64, 256, sm1>>>(x, c, bs, bb, bm, bv, W0, b0, W1, b1, out, N);
    k_spline_mma<<<N / 128, 256, sm2>>>(x, out, N);
}

// round 6
// speedup vs baseline: 1.3095x; 1.3095x over previous
#include <cuda_runtime.h>
#include <cuda_bf16.h>
#include <math.h>
#include <stdint.h>

#define NMAX 65536
#define SA 136                    // tile stride in halves (ldmatrix conflict-free)
#define P_STRIDE 50
#define BH48H (48 * SA)           // halves per split per dim (48-col packed)
#define BBUF48 (2 * BH48H)        // hi+lo halves per dim
#define BD_BYTES (BBUF48 * 2)     // 26112 bytes per dim
#define BH48_BYTES (BH48H * 2)    // 13056

// h2 scratch as bf16 hi/lo splits, transposed: [f * N + row]
__device__ __nv_bfloat16 g_h2_hi[128 * NMAX];
__device__ __nv_bfloat16 g_h2_lo[128 * NMAX];
// Pre-split W2 tiles: per j (32): [hi: 48xSA][lo: 48xSA], n-major, zero-padded
__device__ __nv_bfloat16 g_w2s[32 * BBUF48];
// Padded bias: [32][48]
__device__ float g_b2p[32 * 48];

__device__ __forceinline__ float swishf(float v) {
    return __fdividef(v, 1.0f + __expf(-v));
}

__device__ __forceinline__ void split_bf16(float v, __nv_bfloat16* h, __nv_bfloat16* l) {
    __nv_bfloat16 hh = __float2bfloat16(v);
    *h = hh;
    *l = __float2bfloat16(v - __bfloat162float(hh));
}

__device__ __forceinline__ void mma16816(float* c, const uint32_t* a,
                                         uint32_t b0, uint32_t b1) {
    asm volatile(
        "mma.sync.aligned.m16n8k16.row.col.f32.bf16.bf16.f32 "
        "{%0,%1,%2,%3}, {%4,%5,%6,%7}, {%8,%9}, {%0,%1,%2,%3};"
        : "+f"(c[0]), "+f"(c[1]), "+f"(c[2]), "+f"(c[3])
        : "r"(a[0]), "r"(a[1]), "r"(a[2]), "r"(a[3]), "r"(b0), "r"(b1));
}

#define LDSM4(d, addr)                                                       \
    asm volatile("ldmatrix.sync.aligned.m8n8.x4.shared.b16 {%0,%1,%2,%3}, [%4];" \
        : "=r"((d)[0]), "=r"((d)[1]), "=r"((d)[2]), "=r"((d)[3]) : "r"(addr))

__device__ __forceinline__ uint32_t smem_u32(const void* p) {
    uint32_t a;
    asm("{ .reg .u64 t; cvta.to.shared.u64 t, %1; cvt.u32.u64 %0, t; }" : "=r"(a) : "l"(p));
    return a;
}

// ---------------------------------------------------------------------------
// Prep: split W2 into bf16 hi/lo 48-col tiles (n-major, padded) + padded bias
// ---------------------------------------------------------------------------
__global__ __launch_bounds__(256)
void k_prep(const float* __restrict__ W2, const float* __restrict__ b2)
{
    int idx = blockIdx.x * 256 + threadIdx.x;
    if (idx < 32 * BH48H) {
        int j = idx / BH48H;
        int rem = idx - j * BH48H;
        int n = rem / SA;
        int k = rem - n * SA;
        float v = (n < 47 && k < 128) ? W2[(size_t)k * 1504 + j * 47 + n] : 0.0f;
        __nv_bfloat16 h, l;
        split_bf16(v, &h, &l);
        g_w2s[(size_t)j * BBUF48 + rem]          = h;
        g_w2s[(size_t)j * BBUF48 + BH48H + rem]  = l;
    }
    if (idx < 32 * 48) {
        int j = idx / 48, cc = idx - j * 48;
        g_b2p[idx] = (cc < 47) ? b2[j * 47 + cc] : 0.0f;
    }
}

// ---------------------------------------------------------------------------
// Kernel 1: BN + Dense(48->128)+swish + Dense(128->128)+swish -> bf16 hi/lo
// ---------------------------------------------------------------------------
__global__ __launch_bounds__(256)
void k_mlp(const float* __restrict__ x, const float* __restrict__ c,
           const float* __restrict__ bn_scale, const float* __restrict__ bn_bias,
           const float* __restrict__ bn_mean, const float* __restrict__ bn_var,
           const float* __restrict__ W0, const float* __restrict__ b0,
           const float* __restrict__ W1, const float* __restrict__ b1,
           float* __restrict__ out, int N)
{
    extern __shared__ float sm[];
    float* W0s = sm;
    float* W1s = W0s + 48 * 128;
    float* b0s = W1s + 128 * 128;
    float* b1s = b0s + 128;
    float* ab  = b1s + 128;
    float* A0s = ab + 96;
    float* A1s = A0s + 48 * 65;
    float* A2s = A1s + 128 * 65;

    const int tid  = threadIdx.x;
    const int row0 = blockIdx.x * 64;

    for (int i = tid; i < 48 * 128; i += 256)  W0s[i] = W0[i];
    for (int i = tid; i < 128 * 128; i += 256) W1s[i] = W1[i];
    if (tid < 128) { b0s[tid] = b0[tid]; b1s[tid] = b1[tid]; }
    if (tid < 48) {
        float a = bn_scale[tid] * rsqrtf(bn_var[tid] + 1e-5f);
        ab[tid]      = a;
        ab[48 + tid] = bn_bias[tid] - bn_mean[tid] * a;
    }
    __syncthreads();

    for (int idx = tid; idx < 64 * 32; idx += 256) {
        int k = idx & 31, r = idx >> 5;
        float v = x[(size_t)(row0 + r) * 64 + 32 + k];
        out[(size_t)(row0 + r) * 64 + 32 + k] = v;
        A0s[k * 65 + r] = v * ab[k] + ab[48 + k];
    }
    for (int idx = tid; idx < 64 * 16; idx += 256) {
        int k = idx & 15, r = idx >> 4;
        float v = c[(size_t)(row0 + r) * 16 + k];
        int kk = 32 + k;
        A0s[kk * 65 + r] = v * ab[kk] + ab[48 + kk];
    }
    __syncthreads();

    const int rt = tid >> 4, ct = tid & 15;
    const int r0 = rt * 4, f0 = ct * 8;

    {
        float acc[4][8];
        #pragma unroll
        for (int i = 0; i < 4; i++)
            #pragma unroll
            for (int q = 0; q < 8; q++) acc[i][q] = 0.0f;
        #pragma unroll 4
        for (int k = 0; k < 48; k++) {
            float a0 = A0s[k * 65 + r0 + 0];
            float a1 = A0s[k * 65 + r0 + 1];
            float a2 = A0s[k * 65 + r0 + 2];
            float a3 = A0s[k * 65 + r0 + 3];
            float4 wA = *(const float4*)&W0s[k * 128 + f0];
            float4 wB = *(const float4*)&W0s[k * 128 + f0 + 4];
            float w[8] = {wA.x, wA.y, wA.z, wA.w, wB.x, wB.y, wB.z, wB.w};
            #pragma unroll
            for (int q = 0; q < 8; q++) {
                acc[0][q] += a0 * w[q]; acc[1][q] += a1 * w[q];
                acc[2][q] += a2 * w[q]; acc[3][q] += a3 * w[q];
            }
        }
        #pragma unroll
        for (int q = 0; q < 8; q++) {
            float bb = b0s[f0 + q];
            #pragma unroll
            for (int i = 0; i < 4; i++)
                A1s[(f0 + q) * 65 + (r0 + i)] = swishf(acc[i][q] + bb);
        }
    }
    __syncthreads();

    {
        float acc[4][8];
        #pragma unroll
        for (int i = 0; i < 4; i++)
            #pragma unroll
            for (int q = 0; q < 8; q++) acc[i][q] = 0.0f;
        #pragma unroll 4
        for (int k = 0; k < 128; k++) {
            float a0 = A1s[k * 65 + r0 + 0];
            float a1 = A1s[k * 65 + r0 + 1];
            float a2 = A1s[k * 65 + r0 + 2];
            float a3 = A1s[k * 65 + r0 + 3];
            float4 wA = *(const float4*)&W1s[k * 128 + f0];
            float4 wB = *(const float4*)&W1s[k * 128 + f0 + 4];
            float w[8] = {wA.x, wA.y, wA.z, wA.w, wB.x, wB.y, wB.z, wB.w};
            #pragma unroll
            for (int q = 0; q < 8; q++) {
                acc[0][q] += a0 * w[q]; acc[1][q] += a1 * w[q];
                acc[2][q] += a2 * w[q]; acc[3][q] += a3 * w[q];
            }
        }
        #pragma unroll
        for (int q = 0; q < 8; q++) {
            float bb = b1s[f0 + q];
            #pragma unroll
            for (int i = 0; i < 4; i++)
                A2s[(f0 + q) * 64 + (r0 + i)] = swishf(acc[i][q] + bb);
        }
    }
    __syncthreads();

    for (int idx = tid; idx < 128 * 64; idx += 256) {
        int f = idx >> 6, r = idx & 63;
        float v = A2s[idx];
        __nv_bfloat16 h, l;
        split_bf16(v, &h, &l);
        g_h2_hi[(size_t)f * N + row0 + r] = h;
        g_h2_lo[(size_t)f * N + row0 + r] = l;
    }
}

// ---------------------------------------------------------------------------
// Kernel 2: HMMA, 48-col packed, A-hi in regs, A-lo in smem, 2 blocks/SM.
// smem: [A-lo 34816][P 128x50 f32 = 25600][B dbl buf 2x26112] = 112640 B
// ---------------------------------------------------------------------------
#define SM_ALO 0u
#define SM_P   34816u
#define SM_B   60416u
#define SM_TOT 112640u

__global__ __launch_bounds__(256, 2)
void k_spline_mma(const float* __restrict__ x, float* __restrict__ out, int N)
{
    extern __shared__ char smem[];
    __nv_bfloat16* ALo = (__nv_bfloat16*)(smem + SM_ALO);
    float* P = (float*)(smem + SM_P);

    const int tid  = threadIdx.x;
    const int warp = tid >> 5;
    const int lane = tid & 31;
    const int g    = lane >> 2;
    const int c2   = lane & 3;
    const int r0   = warp * 16;
    const int row0 = blockIdx.x * 128;

    const uint32_t sb  = smem_u32(smem);
    const uint32_t sbB = sb + SM_B;

    // ---- Stage A: hi transiently into B region, lo into its permanent region
    {
        __nv_bfloat16* AHs = (__nv_bfloat16*)(smem + SM_B);
        for (int idx = tid; idx < 128 * 32; idx += 256) {
            int k = idx >> 5, r4 = (idx & 31) * 4;
            size_t gaddr = (size_t)k * N + row0 + r4;
            #pragma unroll
            for (int q = 0; q < 4; q++) {
                AHs[(r4 + q) * SA + k] = g_h2_hi[gaddr + q];
                ALo[(r4 + q) * SA + k] = g_h2_lo[gaddr + q];
            }
        }
    }
    __syncthreads();

    // ---- LDSM all A-hi fragments into registers (8 ks x 4 regs)
    uint32_t afh[8][4];
    const uint32_t a_frag_off = (uint32_t)(((r0 + (lane & 15)) * SA + ((lane >> 4) << 3)) * 2);
    {
        uint32_t a_addr = sbB + a_frag_off;
        #pragma unroll
        for (int ks = 0; ks < 8; ks++)
            LDSM4(afh[ks], a_addr + ks * 32);
    }
    __syncthreads();   // A-hi staging dead; B region free for cp.async

    // ---- Prefetch B(0) (1632 x 16B chunks)
    {
        const char* bsrc = (const char*)g_w2s;
        #pragma unroll
        for (int it = 0; it < 7; it++) {
            int ch = tid + it * 256;
            if (ch < 1632) {
                asm volatile("cp.async.cg.shared.global [%0], [%1], 16;"
                             :: "r"(sbB + ch * 16), "l"(bsrc + ch * 16) : "memory");
            }
        }
        asm volatile("cp.async.commit_group;" ::: "memory");
    }

    // Per-thread B ldmatrix offset components
    const uint32_t b_noff = (uint32_t)(((lane & 7) + ((lane >> 4) << 3)) * SA * 2);
    const uint32_t b_koff = (uint32_t)(((lane >> 3) & 1) << 4);
    const uint32_t alo_addr = sb + SM_ALO + a_frag_off;

    float logdet = 0.0f;
    const int myrow = r0 + lane;           // spline row (lane < 16)
    const size_t grow = (size_t)(row0 + myrow);

    for (int j = 0; j < 32; j++) {
        asm volatile("cp.async.wait_group 0;" ::: "memory");
        __syncthreads();   // B(j) visible; P(j-1) reads done block-wide

        // ---- Prefetch B(j+1)
        if (j + 1 < 32) {
            uint32_t bdst = sbB + ((j + 1) & 1) * BD_BYTES;
            const char* bsrc = (const char*)(g_w2s + (size_t)(j + 1) * BBUF48);
            #pragma unroll
            for (int it = 0; it < 7; it++) {
                int ch = tid + it * 256;
                if (ch < 1632) {
                    asm volatile("cp.async.cg.shared.global [%0], [%1], 16;"
                                 :: "r"(bdst + ch * 16), "l"(bsrc + ch * 16) : "memory");
                }
            }
        }
        asm volatile("cp.async.commit_group;" ::: "memory");

        // ---- GEMM: 16 rows x 48 cols, 3 split terms
        const uint32_t bh_base = sbB + (j & 1) * BD_BYTES + b_noff + b_koff;
        const uint32_t bl_base = bh_base + BH48_BYTES;

        float acc[6][4];
        #pragma unroll
        for (int t = 0; t < 6; t++)
            #pragma unroll
            for (int q = 0; q < 4; q++) acc[t][q] = 0.0f;

        #pragma unroll
        for (int ks = 0; ks < 8; ks++) {
            uint32_t afl[4];
            LDSM4(afl, alo_addr + ks * 32);
            uint32_t bh[3][4], bl[3][4];
            #pragma unroll
            for (int t2 = 0; t2 < 3; t2++) {
                uint32_t o = (uint32_t)(t2 * 16 * SA * 2 + ks * 32);
                LDSM4(bh[t2], bh_base + o);
                LDSM4(bl[t2], bl_base + o);
            }
            #pragma unroll
            for (int t2 = 0; t2 < 3; t2++) {
                mma16816(acc[2 * t2],     afh[ks], bh[t2][0], bh[t2][1]);  // hi*hi
                mma16816(acc[2 * t2],     afl,     bh[t2][0], bh[t2][1]);  // lo*hi
                mma16816(acc[2 * t2],     afh[ks], bl[t2][0], bl[t2][1]);  // hi*lo
                mma16816(acc[2 * t2 + 1], afh[ks], bh[t2][2], bh[t2][3]);
                mma16816(acc[2 * t2 + 1], afl,     bh[t2][2], bh[t2][3]);
                mma16816(acc[2 * t2 + 1], afh[ks], bl[t2][2], bl[t2][3]);
            }
        }

        // ---- Epilogue: bias (global, L1-hot), exp for softmax cols (<32)
        const float* bj = &g_b2p[j * 48];
        #pragma unroll
        for (int t = 0; t < 6; t++) {
            int cb = 8 * t + 2 * c2;
            float2 bb = *(const float2*)&bj[cb];
            float v00 = acc[t][0] + bb.x, v01 = acc[t][1] + bb.y;
            float v10 = acc[t][2] + bb.x, v11 = acc[t][3] + bb.y;
            if (t < 4) {
                v00 = __expf(v00); v01 = __expf(v01);
                v10 = __expf(v10); v11 = __expf(v11);
            }
            *(float2*)&P[(r0 + g) * P_STRIDE + cb]     = make_float2(v00, v01);
            *(float2*)&P[(r0 + g + 8) * P_STRIDE + cb] = make_float2(v10, v11);
        }
        __syncwarp();

        // ---- Spline: warp-local, lanes 0..15 (one per row)
        if (lane < 16) {
            const float* pr = &P[myrow * P_STRIDE];
            float tin = __ldg(&x[grow * 64 + j]);

            float sW = 0.0f, sH = 0.0f;
            #pragma unroll
            for (int i = 0; i < 16; i++) { sW += pr[i]; sH += pr[16 + i]; }
            float invW = __fdividef(1.0f, sW);
            float invH = __fdividef(1.0f, sH);

            float tc  = fminf(fmaxf(tin, 0.0f), 1.0f);
            bool  inb = (tin >= 0.0f) && (tin <= 1.0f);

            float xk = 0.0f, cy = 0.0f;
            float xk_b = 0.0f, yk_b = 0.0f;
            float dx_b = pr[0] * invW, dy_b = pr[16] * invH;
            int bidx = 0;
            #pragma unroll
            for (int i = 0; i < 16; i++) {
                float dxi = pr[i] * invW;
                float dyi = pr[16 + i] * invH;
                if (xk <= tc) { bidx = i; xk_b = xk; dx_b = dxi; yk_b = cy; dy_b = dyi; }
                xk += dxi; cy += dyi;
            }

            float v0 = pr[32 + ((bidx > 0) ? bidx - 1 : 0)];
            float v1 = pr[32 + ((bidx < 15) ? bidx : 14)];
            float sp0 = fmaxf(v0, 0.0f) + __logf(1.0f + __expf(-fabsf(v0)));
            float sp1 = fmaxf(v1, 0.0f) + __logf(1.0f + __expf(-fabsf(v1)));
            float d0 = (bidx == 0)  ? 1.0f : sp0;
            float d1 = (bidx == 15) ? 1.0f : sp1;

            float xi   = __fdividef(tc - xk_b, dx_b);
            float s    = __fdividef(dy_b, dx_b);
            float xi1m = xi * (1.0f - xi);
            float den  = s + (d0 + d1 - 2.0f * s) * xi1m;
            float num  = s * xi * xi + d0 * xi1m;
            float y_in = yk_b + dy_b * __fdividef(num, den);
            float omxi = 1.0f - xi;
            float dnum = d1 * xi * xi + 2.0f * s * xi1m + d0 * omxi * omxi;
            float dydx = __fdividef(s * s * dnum, den * den);

            out[grow * 64 + j] = inb ? y_in : tin;
            logdet += inb ? __logf(dydx) : 0.0f;
        }
        __syncwarp();
    }

    if (lane < 16)
        out[(size_t)N * 64 + row0 + myrow] = logdet;
}

// ---------------------------------------------------------------------------
extern "C" void kernel_launch(void* const* d_in, const int* in_sizes, int n_in,
                              void* d_out, int out_size)
{
    const float* x  = (const float*)d_in[0];
    const float* c  = (const float*)d_in[1];
    const float* bs = (const float*)d_in[2];
    const float* bb = (const float*)d_in[3];
    const float* bm = (const float*)d_in[4];
    const float* bv = (const float*)d_in[5];
    const float* W0 = (const float*)d_in[6];
    const float* b0 = (const float*)d_in[7];
    const float* W1 = (const float*)d_in[8];
    const float* b1 = (const float*)d_in[9];
    const float* W2 = (const float*)d_in[10];
    const float* b2 = (const float*)d_in[11];
    float* out = (float*)d_out;

    int N = in_sizes[0] / 64;

    size_t sm1 = (size_t)(48*128 + 128*128 + 128 + 128 + 96 + 48*65 + 128*65 + 128*64) * sizeof(float);

    cudaFuncSetAttribute(k_mlp,        cudaFuncAttributeMaxDynamicSharedMemorySize, (int)sm1);
    cudaFuncSetAttribute(k_spline_mma, cudaFuncAttributeMaxDynamicSharedMemorySize, (int)SM_TOT);

    k_prep<<<(32 * BH48H + 255) / 256, 256>>>(W2, b2);
    k_mlp<<<N / 64, 256, sm1>>>(x, c, bs, bb, bm, bv, W0, b0, W1, b1, out, N);
    k_spline_mma<<<N / 128, 256, SM_TOT>>>(x, out, N);
}

// round 7
// speedup vs baseline: 1.5026x; 1.1474x over previous
#include <cuda_runtime.h>
#include <cuda_fp16.h>
#include <math.h>
#include <stdint.h>

#define NMAX 65536
#define SA 136                    // tile stride in halves (ldmatrix conflict-free)
#define P_STRIDE 50
#define BH48H (48 * SA)           // halves per dim tile (48-col packed, fp16 single)
#define BD_BYTES (BH48H * 2)      // 13056 bytes per dim

// h2 scratch as fp16 hi/lo splits, transposed: [f * N + row]
__device__ __half g_h2_hi[128 * NMAX];
__device__ __half g_h2_lo[128 * NMAX];
// W2 tiles: per j (32): 48 x SA fp16, n-major, zero-padded
__device__ __half g_w2s[32 * BH48H];
// Padded bias: [32][48]
__device__ float g_b2p[32 * 48];

__device__ __forceinline__ float swishf(float v) {
    return __fdividef(v, 1.0f + __expf(-v));
}

__device__ __forceinline__ void split_fp16(float v, __half* h, __half* l) {
    __half hh = __float2half_rn(v);
    *h = hh;
    *l = __float2half_rn(v - __half2float(hh));
}

__device__ __forceinline__ void mma16816(float* c, const uint32_t* a,
                                         uint32_t b0, uint32_t b1) {
    asm volatile(
        "mma.sync.aligned.m16n8k16.row.col.f32.f16.f16.f32 "
        "{%0,%1,%2,%3}, {%4,%5,%6,%7}, {%8,%9}, {%0,%1,%2,%3};"
        : "+f"(c[0]), "+f"(c[1]), "+f"(c[2]), "+f"(c[3])
        : "r"(a[0]), "r"(a[1]), "r"(a[2]), "r"(a[3]), "r"(b0), "r"(b1));
}

#define LDSM4(d, addr)                                                       \
    asm volatile("ldmatrix.sync.aligned.m8n8.x4.shared.b16 {%0,%1,%2,%3}, [%4];" \
        : "=r"((d)[0]), "=r"((d)[1]), "=r"((d)[2]), "=r"((d)[3]) : "r"(addr))

__device__ __forceinline__ uint32_t smem_u32(const void* p) {
    uint32_t a;
    asm("{ .reg .u64 t; cvta.to.shared.u64 t, %1; cvt.u32.u64 %0, t; }" : "=r"(a) : "l"(p));
    return a;
}

// ---------------------------------------------------------------------------
// Prep: W2 -> fp16 48-col tiles (n-major, padded) + padded bias
// ---------------------------------------------------------------------------
__global__ __launch_bounds__(256)
void k_prep(const float* __restrict__ W2, const float* __restrict__ b2)
{
    int idx = blockIdx.x * 256 + threadIdx.x;
    if (idx < 32 * BH48H) {
        int j = idx / BH48H;
        int rem = idx - j * BH48H;
        int n = rem / SA;
        int k = rem - n * SA;
        float v = (n < 47 && k < 128) ? W2[(size_t)k * 1504 + j * 47 + n] : 0.0f;
        g_w2s[idx] = __float2half_rn(v);
    }
    if (idx < 32 * 48) {
        int j = idx / 48, cc = idx - j * 48;
        g_b2p[idx] = (cc < 47) ? b2[j * 47 + cc] : 0.0f;
    }
}

// ---------------------------------------------------------------------------
// Kernel 1: BN + Dense(48->128)+swish + Dense(128->128)+swish -> fp16 hi/lo
// ---------------------------------------------------------------------------
__global__ __launch_bounds__(256)
void k_mlp(const float* __restrict__ x, const float* __restrict__ c,
           const float* __restrict__ bn_scale, const float* __restrict__ bn_bias,
           const float* __restrict__ bn_mean, const float* __restrict__ bn_var,
           const float* __restrict__ W0, const float* __restrict__ b0,
           const float* __restrict__ W1, const float* __restrict__ b1,
           float* __restrict__ out, int N)
{
    extern __shared__ float sm[];
    float* W0s = sm;
    float* W1s = W0s + 48 * 128;
    float* b0s = W1s + 128 * 128;
    float* b1s = b0s + 128;
    float* ab  = b1s + 128;
    float* A0s = ab + 96;
    float* A1s = A0s + 48 * 65;
    float* A2s = A1s + 128 * 65;

    const int tid  = threadIdx.x;
    const int row0 = blockIdx.x * 64;

    for (int i = tid; i < 48 * 128; i += 256)  W0s[i] = W0[i];
    for (int i = tid; i < 128 * 128; i += 256) W1s[i] = W1[i];
    if (tid < 128) { b0s[tid] = b0[tid]; b1s[tid] = b1[tid]; }
    if (tid < 48) {
        float a = bn_scale[tid] * rsqrtf(bn_var[tid] + 1e-5f);
        ab[tid]      = a;
        ab[48 + tid] = bn_bias[tid] - bn_mean[tid] * a;
    }
    __syncthreads();

    for (int idx = tid; idx < 64 * 32; idx += 256) {
        int k = idx & 31, r = idx >> 5;
        float v = x[(size_t)(row0 + r) * 64 + 32 + k];
        out[(size_t)(row0 + r) * 64 + 32 + k] = v;
        A0s[k * 65 + r] = v * ab[k] + ab[48 + k];
    }
    for (int idx = tid; idx < 64 * 16; idx += 256) {
        int k = idx & 15, r = idx >> 4;
        float v = c[(size_t)(row0 + r) * 16 + k];
        int kk = 32 + k;
        A0s[kk * 65 + r] = v * ab[kk] + ab[48 + kk];
    }
    __syncthreads();

    const int rt = tid >> 4, ct = tid & 15;
    const int r0 = rt * 4, f0 = ct * 8;

    {
        float acc[4][8];
        #pragma unroll
        for (int i = 0; i < 4; i++)
            #pragma unroll
            for (int q = 0; q < 8; q++) acc[i][q] = 0.0f;
        #pragma unroll 4
        for (int k = 0; k < 48; k++) {
            float a0 = A0s[k * 65 + r0 + 0];
            float a1 = A0s[k * 65 + r0 + 1];
            float a2 = A0s[k * 65 + r0 + 2];
            float a3 = A0s[k * 65 + r0 + 3];
            float4 wA = *(const float4*)&W0s[k * 128 + f0];
            float4 wB = *(const float4*)&W0s[k * 128 + f0 + 4];
            float w[8] = {wA.x, wA.y, wA.z, wA.w, wB.x, wB.y, wB.z, wB.w};
            #pragma unroll
            for (int q = 0; q < 8; q++) {
                acc[0][q] += a0 * w[q]; acc[1][q] += a1 * w[q];
                acc[2][q] += a2 * w[q]; acc[3][q] += a3 * w[q];
            }
        }
        #pragma unroll
        for (int q = 0; q < 8; q++) {
            float bb = b0s[f0 + q];
            #pragma unroll
            for (int i = 0; i < 4; i++)
                A1s[(f0 + q) * 65 + (r0 + i)] = swishf(acc[i][q] + bb);
        }
    }
    __syncthreads();

    {
        float acc[4][8];
        #pragma unroll
        for (int i = 0; i < 4; i++)
            #pragma unroll
            for (int q = 0; q < 8; q++) acc[i][q] = 0.0f;
        #pragma unroll 4
        for (int k = 0; k < 128; k++) {
            float a0 = A1s[k * 65 + r0 + 0];
            float a1 = A1s[k * 65 + r0 + 1];
            float a2 = A1s[k * 65 + r0 + 2];
            float a3 = A1s[k * 65 + r0 + 3];
            float4 wA = *(const float4*)&W1s[k * 128 + f0];
            float4 wB = *(const float4*)&W1s[k * 128 + f0 + 4];
            float w[8] = {wA.x, wA.y, wA.z, wA.w, wB.x, wB.y, wB.z, wB.w};
            #pragma unroll
            for (int q = 0; q < 8; q++) {
                acc[0][q] += a0 * w[q]; acc[1][q] += a1 * w[q];
                acc[2][q] += a2 * w[q]; acc[3][q] += a3 * w[q];
            }
        }
        #pragma unroll
        for (int q = 0; q < 8; q++) {
            float bb = b1s[f0 + q];
            #pragma unroll
            for (int i = 0; i < 4; i++)
                A2s[(f0 + q) * 64 + (r0 + i)] = swishf(acc[i][q] + bb);
        }
    }
    __syncthreads();

    for (int idx = tid; idx < 128 * 64; idx += 256) {
        int f = idx >> 6, r = idx & 63;
        float v = A2s[idx];
        __half h, l;
        split_fp16(v, &h, &l);
        g_h2_hi[(size_t)f * N + row0 + r] = h;
        g_h2_lo[(size_t)f * N + row0 + r] = l;
    }
}

// ---------------------------------------------------------------------------
// Kernel 2: fp16 HMMA, 2-term A-split, B single fp16. 2 blocks/SM.
// smem: [A-lo 34816][P 128x50 f32 = 25600][B dbl buf 2x13056] = 86528 B
// (A-hi staged transiently in the P+B region during prologue)
// ---------------------------------------------------------------------------
#define SM_ALO 0u
#define SM_P   34816u
#define SM_B   60416u
#define SM_TOT 86528u

__global__ __launch_bounds__(256, 2)
void k_spline_mma(const float* __restrict__ x, float* __restrict__ out, int N)
{
    extern __shared__ char smem[];
    __half* ALo = (__half*)(smem + SM_ALO);
    float* P = (float*)(smem + SM_P);

    const int tid  = threadIdx.x;
    const int warp = tid >> 5;
    const int lane = tid & 31;
    const int g    = lane >> 2;
    const int c2   = lane & 3;
    const int r0   = warp * 16;
    const int row0 = blockIdx.x * 128;

    const uint32_t sb  = smem_u32(smem);
    const uint32_t sbB = sb + SM_B;

    // ---- Stage A: hi transiently into P+B region, lo into its permanent region
    {
        __half* AHs = (__half*)(smem + SM_P);   // 34816B fits in P+B (38912B)
        for (int idx = tid; idx < 128 * 32; idx += 256) {
            int k = idx >> 5, r4 = (idx & 31) * 4;
            size_t gaddr = (size_t)k * N + row0 + r4;
            #pragma unroll
            for (int q = 0; q < 4; q++) {
                AHs[(r4 + q) * SA + k] = g_h2_hi[gaddr + q];
                ALo[(r4 + q) * SA + k] = g_h2_lo[gaddr + q];
            }
        }
    }
    __syncthreads();

    // ---- LDSM all A-hi fragments into registers (8 ks x 4 regs)
    uint32_t afh[8][4];
    const uint32_t a_frag_off = (uint32_t)(((r0 + (lane & 15)) * SA + ((lane >> 4) << 3)) * 2);
    {
        uint32_t a_addr = sb + SM_P + a_frag_off;
        #pragma unroll
        for (int ks = 0; ks < 8; ks++)
            LDSM4(afh[ks], a_addr + ks * 32);
    }
    __syncthreads();   // A-hi staging dead; P/B regions free

    // ---- Prefetch B(0) (816 x 16B chunks)
    {
        const char* bsrc = (const char*)g_w2s;
        #pragma unroll
        for (int it = 0; it < 4; it++) {
            int ch = tid + it * 256;
            if (ch < 816) {
                asm volatile("cp.async.cg.shared.global [%0], [%1], 16;"
                             :: "r"(sbB + ch * 16), "l"(bsrc + ch * 16) : "memory");
            }
        }
        asm volatile("cp.async.commit_group;" ::: "memory");
    }

    // Per-thread B ldmatrix offset components
    const uint32_t b_noff = (uint32_t)(((lane & 7) + ((lane >> 4) << 3)) * SA * 2);
    const uint32_t b_koff = (uint32_t)(((lane >> 3) & 1) << 4);
    const uint32_t alo_addr = sb + SM_ALO + a_frag_off;

    float logdet = 0.0f;
    const int myrow = r0 + lane;           // spline row (lane < 16)
    const size_t grow = (size_t)(row0 + myrow);

    for (int j = 0; j < 32; j++) {
        asm volatile("cp.async.wait_group 0;" ::: "memory");
        __syncthreads();   // B(j) visible; P(j-1) reads done block-wide

        // ---- Prefetch B(j+1)
        if (j + 1 < 32) {
            uint32_t bdst = sbB + ((j + 1) & 1) * BD_BYTES;
            const char* bsrc = (const char*)(g_w2s + (size_t)(j + 1) * BH48H);
            #pragma unroll
            for (int it = 0; it < 4; it++) {
                int ch = tid + it * 256;
                if (ch < 816) {
                    asm volatile("cp.async.cg.shared.global [%0], [%1], 16;"
                                 :: "r"(bdst + ch * 16), "l"(bsrc + ch * 16) : "memory");
                }
            }
        }
        asm volatile("cp.async.commit_group;" ::: "memory");

        // ---- GEMM: 16 rows x 48 cols, 2 split terms (Ah*B + Al*B)
        const uint32_t bh_base = sbB + (j & 1) * BD_BYTES + b_noff + b_koff;

        float acc[6][4];
        #pragma unroll
        for (int t = 0; t < 6; t++)
            #pragma unroll
            for (int q = 0; q < 4; q++) acc[t][q] = 0.0f;

        #pragma unroll
        for (int ks = 0; ks < 8; ks++) {
            uint32_t afl[4];
            LDSM4(afl, alo_addr + ks * 32);
            uint32_t bh[3][4];
            #pragma unroll
            for (int t2 = 0; t2 < 3; t2++) {
                uint32_t o = (uint32_t)(t2 * 16 * SA * 2 + ks * 32);
                LDSM4(bh[t2], bh_base + o);
            }
            #pragma unroll
            for (int t2 = 0; t2 < 3; t2++) {
                mma16816(acc[2 * t2],     afh[ks], bh[t2][0], bh[t2][1]);
                mma16816(acc[2 * t2],     afl,     bh[t2][0], bh[t2][1]);
                mma16816(acc[2 * t2 + 1], afh[ks], bh[t2][2], bh[t2][3]);
                mma16816(acc[2 * t2 + 1], afl,     bh[t2][2], bh[t2][3]);
            }
        }

        // ---- Epilogue: bias (global, L1-hot), exp for softmax cols (<32)
        const float* bj = &g_b2p[j * 48];
        #pragma unroll
        for (int t = 0; t < 6; t++) {
            int cb = 8 * t + 2 * c2;
            float2 bb = *(const float2*)&bj[cb];
            float v00 = acc[t][0] + bb.x, v01 = acc[t][1] + bb.y;
            float v10 = acc[t][2] + bb.x, v11 = acc[t][3] + bb.y;
            if (t < 4) {
                v00 = __expf(v00); v01 = __expf(v01);
                v10 = __expf(v10); v11 = __expf(v11);
            }
            *(float2*)&P[(r0 + g) * P_STRIDE + cb]     = make_float2(v00, v01);
            *(float2*)&P[(r0 + g + 8) * P_STRIDE + cb] = make_float2(v10, v11);
        }
        __syncwarp();

        // ---- Spline: warp-local, lanes 0..15 (one per row)
        if (lane < 16) {
            const float* pr = &P[myrow * P_STRIDE];
            float tin = __ldg(&x[grow * 64 + j]);

            float sW = 0.0f, sH = 0.0f;
            #pragma unroll
            for (int i = 0; i < 16; i++) { sW += pr[i]; sH += pr[16 + i]; }
            float invW = __fdividef(1.0f, sW);
            float invH = __fdividef(1.0f, sH);

            float tc  = fminf(fmaxf(tin, 0.0f), 1.0f);
            bool  inb = (tin >= 0.0f) && (tin <= 1.0f);

            float xk = 0.0f, cy = 0.0f;
            float xk_b = 0.0f, yk_b = 0.0f;
            float dx_b = pr[0] * invW, dy_b = pr[16] * invH;
            int bidx = 0;
            #pragma unroll
            for (int i = 0; i < 16; i++) {
                float dxi = pr[i] * invW;
                float dyi = pr[16 + i] * invH;
                if (xk <= tc) { bidx = i; xk_b = xk; dx_b = dxi; yk_b = cy; dy_b = dyi; }
                xk += dxi; cy += dyi;
            }

            float v0 = pr[32 + ((bidx > 0) ? bidx - 1 : 0)];
            float v1 = pr[32 + ((bidx < 15) ? bidx : 14)];
            float sp0 = fmaxf(v0, 0.0f) + __logf(1.0f + __expf(-fabsf(v0)));
            float sp1 = fmaxf(v1, 0.0f) + __logf(1.0f + __expf(-fabsf(v1)));
            float d0 = (bidx == 0)  ? 1.0f : sp0;
            float d1 = (bidx == 15) ? 1.0f : sp1;

            float xi   = __fdividef(tc - xk_b, dx_b);
            float s    = __fdividef(dy_b, dx_b);
            float xi1m = xi * (1.0f - xi);
            float den  = s + (d0 + d1 - 2.0f * s) * xi1m;
            float num  = s * xi * xi + d0 * xi1m;
            float y_in = yk_b + dy_b * __fdividef(num, den);
            float omxi = 1.0f - xi;
            float dnum = d1 * xi * xi + 2.0f * s * xi1m + d0 * omxi * omxi;
            float dydx = __fdividef(s * s * dnum, den * den);

            out[grow * 64 + j] = inb ? y_in : tin;
            logdet += inb ? __logf(dydx) : 0.0f;
        }
        __syncwarp();
    }

    if (lane < 16)
        out[(size_t)N * 64 + row0 + myrow] = logdet;
}

// ---------------------------------------------------------------------------
extern "C" void kernel_launch(void* const* d_in, const int* in_sizes, int n_in,
                              void* d_out, int out_size)
{
    const float* x  = (const float*)d_in[0];
    const float* c  = (const float*)d_in[1];
    const float* bs = (const float*)d_in[2];
    const float* bb = (const float*)d_in[3];
    const float* bm = (const float*)d_in[4];
    const float* bv = (const float*)d_in[5];
    const float* W0 = (const float*)d_in[6];
    const float* b0 = (const float*)d_in[7];
    const float* W1 = (const float*)d_in[8];
    const float* b1 = (const float*)d_in[9];
    const float* W2 = (const float*)d_in[10];
    const float* b2 = (const float*)d_in[11];
    float* out = (float*)d_out;

    int N = in_sizes[0] / 64;

    size_t sm1 = (size_t)(48*128 + 128*128 + 128 + 128 + 96 + 48*65 + 128*65 + 128*64) * sizeof(float);

    cudaFuncSetAttribute(k_mlp,        cudaFuncAttributeMaxDynamicSharedMemorySize, (int)sm1);
    cudaFuncSetAttribute(k_spline_mma, cudaFuncAttributeMaxDynamicSharedMemorySize, (int)SM_TOT);

    k_prep<<<(32 * BH48H + 255) / 256, 256>>>(W2, b2);
    k_mlp<<<N / 64, 256, sm1>>>(x, c, bs, bb, bm, bv, W0, b0, W1, b1, out, N);
    k_spline_mma<<<N / 128, 256, SM_TOT>>>(x, out, N);
}

// round 8
// speedup vs baseline: 2.6131x; 1.7391x over previous
#include <cuda_runtime.h>
#include <cuda_fp16.h>
#include <math.h>
#include <stdint.h>

#define SA 136                    // stride (halves) for 128-k tiles
#define S0 56                     // stride (halves) for 48-k tiles
#define P_STRIDE 50
#define BH48H (48 * SA)           // halves per W2 dim tile
#define BD_BYTES (BH48H * 2)      // 13056 bytes per dim

// ---- smem byte offsets (phase-overlaid regions, total 112640) ----
#define O_A1H  0u                 // A1 hi (MLP) -> h2 lo (spline ALo)   34816
#define O_A1L  34816u             // A1 lo -> h2 hi staging -> P         34816
#define O_W1   69632u             // W1 tile (after A0/W0 die)           34816
#define O_A0H  69632u             // A0 hi                               14336
#define O_A0L  83968u             // A0 lo                               14336
#define O_W0   98304u             // W0 tile                             14336
#define O_P    34816u             // P 128 x 50 f32                      25600
#define O_B    60416u             // B double buffer 2 x 13056           26112
#define SM_TOT 112640u

// Pre-converted weights / params (k_prep)
__device__ __half g_w0t[128 * S0];      // W0 n-major [n][k], k<48
__device__ __half g_w1t[128 * SA];      // W1 n-major [n][k], k<128
__device__ __half g_w2s[32 * BH48H];    // W2 tiles per dim, n-major
__device__ float  g_b2p[32 * 48];       // padded b2
__device__ float  g_ab[96];             // BN alpha[48], beta[48]

__device__ __forceinline__ float swishf(float v) {
    return __fdividef(v, 1.0f + __expf(-v));
}

__device__ __forceinline__ void split_fp16(float v, __half* h, __half* l) {
    __half hh = __float2half_rn(v);
    *h = hh;
    *l = __float2half_rn(v - __half2float(hh));
}

__device__ __forceinline__ void mma16816(float* c, const uint32_t* a,
                                         uint32_t b0, uint32_t b1) {
    asm volatile(
        "mma.sync.aligned.m16n8k16.row.col.f32.f16.f16.f32 "
        "{%0,%1,%2,%3}, {%4,%5,%6,%7}, {%8,%9}, {%0,%1,%2,%3};"
        : "+f"(c[0]), "+f"(c[1]), "+f"(c[2]), "+f"(c[3])
        : "r"(a[0]), "r"(a[1]), "r"(a[2]), "r"(a[3]), "r"(b0), "r"(b1));
}

#define LDSM4(d, addr)                                                       \
    asm volatile("ldmatrix.sync.aligned.m8n8.x4.shared.b16 {%0,%1,%2,%3}, [%4];" \
        : "=r"((d)[0]), "=r"((d)[1]), "=r"((d)[2]), "=r"((d)[3]) : "r"(addr))

#define CPASYNC16(dst, src) \
    asm volatile("cp.async.cg.shared.global [%0], [%1], 16;" :: "r"(dst), "l"(src) : "memory")

__device__ __forceinline__ uint32_t smem_u32(const void* p) {
    uint32_t a;
    asm("{ .reg .u64 t; cvta.to.shared.u64 t, %1; cvt.u32.u64 %0, t; }" : "=r"(a) : "l"(p));
    return a;
}

// ---------------------------------------------------------------------------
// Prep: convert all weights to fp16 tiles + BN coefficients + padded bias
// ---------------------------------------------------------------------------
__global__ __launch_bounds__(256)
void k_prep(const float* __restrict__ W0, const float* __restrict__ W1,
            const float* __restrict__ W2, const float* __restrict__ b2,
            const float* __restrict__ bn_scale, const float* __restrict__ bn_bias,
            const float* __restrict__ bn_mean, const float* __restrict__ bn_var)
{
    int idx = blockIdx.x * 256 + threadIdx.x;
    if (idx < 32 * BH48H) {              // W2 tiles
        int j = idx / BH48H;
        int rem = idx - j * BH48H;
        int n = rem / SA;
        int k = rem - n * SA;
        float v = (n < 47 && k < 128) ? W2[(size_t)k * 1504 + j * 47 + n] : 0.0f;
        g_w2s[idx] = __float2half_rn(v);
    }
    if (idx < 128 * SA) {                // W1 tile
        int n = idx / SA, k = idx - n * SA;
        g_w1t[idx] = (k < 128) ? __float2half_rn(W1[(size_t)k * 128 + n]) : __float2half_rn(0.0f);
    }
    if (idx < 128 * S0) {                // W0 tile
        int n = idx / S0, k = idx - n * S0;
        g_w0t[idx] = (k < 48) ? __float2half_rn(W0[(size_t)k * 128 + n]) : __float2half_rn(0.0f);
    }
    if (idx < 32 * 48) {                 // padded b2
        int j = idx / 48, cc = idx - j * 48;
        g_b2p[idx] = (cc < 47) ? b2[j * 47 + cc] : 0.0f;
    }
    if (idx < 48) {                      // BN coefficients
        float a = bn_scale[idx] * rsqrtf(bn_var[idx] + 1e-5f);
        g_ab[idx]      = a;
        g_ab[48 + idx] = bn_bias[idx] - bn_mean[idx] * a;
    }
}

// ---------------------------------------------------------------------------
// Fused kernel: BN + MLP (fp16 HMMA, 2-term A-split) + W2 GEMM + RQS spline.
// Block = 128 rows, 256 threads (8 warps x 16 rows), 2 blocks/SM.
// ---------------------------------------------------------------------------
__global__ __launch_bounds__(256, 2)
void k_fused(const float* __restrict__ x, const float* __restrict__ c,
             const float* __restrict__ b0, const float* __restrict__ b1,
             float* __restrict__ out, int N)
{
    extern __shared__ char smem[];
    const uint32_t sb = smem_u32(smem);

    const int tid  = threadIdx.x;
    const int warp = tid >> 5;
    const int lane = tid & 31;
    const int g    = lane >> 2;
    const int c2   = lane & 3;
    const int r0   = warp * 16;
    const int row0 = blockIdx.x * 128;

    // ---- W0 cp.async (896 x 16B)
    {
        const char* src = (const char*)g_w0t;
        #pragma unroll
        for (int it = 0; it < 4; it++) {
            int ch = tid + it * 256;
            if (ch < 896) CPASYNC16(sb + O_W0 + ch * 16, src + ch * 16);
        }
        asm volatile("cp.async.commit_group;" ::: "memory");
    }

    // ---- Stage A0 (BN'd [xc|c]), warp-local rows, fp16 hi/lo; copy xc -> out
    {
        __half* A0h = (__half*)(smem + O_A0H);
        __half* A0l = (__half*)(smem + O_A0L);
        for (int i = lane; i < 16 * 48; i += 32) {
            int r = i / 48, k = i - (i / 48) * 48;
            size_t rg = (size_t)(row0 + r0 + r);
            float v;
            if (k < 32) { v = x[rg * 64 + 32 + k]; out[rg * 64 + 32 + k] = v; }
            else        { v = c[rg * 16 + (k - 32)]; }
            float a = v * g_ab[k] + g_ab[48 + k];
            __half h, l;
            split_fp16(a, &h, &l);
            A0h[(r0 + r) * S0 + k] = h;
            A0l[(r0 + r) * S0 + k] = l;
        }
    }
    asm volatile("cp.async.wait_group 0;" ::: "memory");
    __syncthreads();   // W0 + all A0 rows visible

    // Fragment address components
    const uint32_t a0_off  = (uint32_t)(((r0 + (lane & 15)) * S0 + ((lane >> 4) << 3)) * 2);
    const uint32_t a1_off  = (uint32_t)(((r0 + (lane & 15)) * SA + ((lane >> 4) << 3)) * 2);
    const uint32_t bn0_off = (uint32_t)((((lane & 7) + ((lane >> 4) << 3)) * S0) * 2 + (((lane >> 3) & 1) << 4));
    const uint32_t bn1_off = (uint32_t)((((lane & 7) + ((lane >> 4) << 3)) * SA) * 2 + (((lane >> 3) & 1) << 4));

    // ================= L0: h1 = swish(A0 @ W0 + b0), 16 rows x 128 cols =====
    {
        float acc[16][4];
        #pragma unroll
        for (int t = 0; t < 16; t++)
            #pragma unroll
            for (int q = 0; q < 4; q++) acc[t][q] = 0.0f;

        const uint32_t a0h_addr = sb + O_A0H + a0_off;
        const uint32_t a0l_addr = sb + O_A0L + a0_off;
        const uint32_t w0_base  = sb + O_W0 + bn0_off;

        #pragma unroll
        for (int ks = 0; ks < 3; ks++) {
            uint32_t ah[4], al[4];
            LDSM4(ah, a0h_addr + ks * 32);
            LDSM4(al, a0l_addr + ks * 32);
            #pragma unroll
            for (int t2 = 0; t2 < 8; t2++) {
                uint32_t bw[4];
                LDSM4(bw, w0_base + t2 * 16 * S0 * 2 + ks * 32);
                mma16816(acc[2 * t2],     ah, bw[0], bw[1]);
                mma16816(acc[2 * t2],     al, bw[0], bw[1]);
                mma16816(acc[2 * t2 + 1], ah, bw[2], bw[3]);
                mma16816(acc[2 * t2 + 1], al, bw[2], bw[3]);
            }
        }

        // Epilogue -> A1 hi/lo (warp-private rows)
        __half* A1h = (__half*)(smem + O_A1H);
        __half* A1l = (__half*)(smem + O_A1L);
        #pragma unroll
        for (int t = 0; t < 16; t++) {
            int cb = 8 * t + 2 * c2;
            float2 bb = __ldg((const float2*)&b0[cb]);
            float v00 = swishf(acc[t][0] + bb.x), v01 = swishf(acc[t][1] + bb.y);
            float v10 = swishf(acc[t][2] + bb.x), v11 = swishf(acc[t][3] + bb.y);
            __half h0, l0, h1, l1;
            split_fp16(v00, &h0, &l0); split_fp16(v01, &h1, &l1);
            *(__half2*)&A1h[(r0 + g) * SA + cb] = __halves2half2(h0, h1);
            *(__half2*)&A1l[(r0 + g) * SA + cb] = __halves2half2(l0, l1);
            split_fp16(v10, &h0, &l0); split_fp16(v11, &h1, &l1);
            *(__half2*)&A1h[(r0 + g + 8) * SA + cb] = __halves2half2(h0, h1);
            *(__half2*)&A1l[(r0 + g + 8) * SA + cb] = __halves2half2(l0, l1);
        }
    }
    __syncthreads();   // all warps done with A0/W0 region

    // ---- W1 cp.async into (dead) A0/W0 region (2176 x 16B)
    {
        const char* src = (const char*)g_w1t;
        #pragma unroll
        for (int it = 0; it < 9; it++) {
            int ch = tid + it * 256;
            if (ch < 2176) CPASYNC16(sb + O_W1 + ch * 16, src + ch * 16);
        }
        asm volatile("cp.async.commit_group;" ::: "memory");
        asm volatile("cp.async.wait_group 0;" ::: "memory");
    }
    __syncthreads();

    // ================= L1: h2 = swish(A1 @ W1 + b1), K=128 ==================
    uint32_t afh[8][4];    // h2 hi fragments (A of the W2 GEMM)
    {
        float acc[16][4];
        #pragma unroll
        for (int t = 0; t < 16; t++)
            #pragma unroll
            for (int q = 0; q < 4; q++) acc[t][q] = 0.0f;

        const uint32_t a1h_addr = sb + O_A1H + a1_off;
        const uint32_t a1l_addr = sb + O_A1L + a1_off;
        const uint32_t w1_base  = sb + O_W1 + bn1_off;

        #pragma unroll
        for (int ks = 0; ks < 8; ks++) {
            uint32_t ah[4], al[4];
            LDSM4(ah, a1h_addr + ks * 32);
            LDSM4(al, a1l_addr + ks * 32);
            #pragma unroll
            for (int t2 = 0; t2 < 8; t2++) {
                uint32_t bw[4];
                LDSM4(bw, w1_base + t2 * 16 * SA * 2 + ks * 32);
                mma16816(acc[2 * t2],     ah, bw[0], bw[1]);
                mma16816(acc[2 * t2],     al, bw[0], bw[1]);
                mma16816(acc[2 * t2 + 1], ah, bw[2], bw[3]);
                mma16816(acc[2 * t2 + 1], al, bw[2], bw[3]);
            }
        }
        __syncwarp();   // own A1 rows consumed; safe to overwrite (warp-local)

        // Epilogue: h2 split; hi -> O_A1L staging, lo -> O_A1H (becomes ALo)
        __half* H2h = (__half*)(smem + O_A1L);
        __half* H2l = (__half*)(smem + O_A1H);
        #pragma unroll
        for (int t = 0; t < 16; t++) {
            int cb = 8 * t + 2 * c2;
            float2 bb = __ldg((const float2*)&b1[cb]);
            float v00 = swishf(acc[t][0] + bb.x), v01 = swishf(acc[t][1] + bb.y);
            float v10 = swishf(acc[t][2] + bb.x), v11 = swishf(acc[t][3] + bb.y);
            __half h0, l0, h1, l1;
            split_fp16(v00, &h0, &l0); split_fp16(v01, &h1, &l1);
            *(__half2*)&H2h[(r0 + g) * SA + cb] = __halves2half2(h0, h1);
            *(__half2*)&H2l[(r0 + g) * SA + cb] = __halves2half2(l0, l1);
            split_fp16(v10, &h0, &l0); split_fp16(v11, &h1, &l1);
            *(__half2*)&H2h[(r0 + g + 8) * SA + cb] = __halves2half2(h0, h1);
            *(__half2*)&H2l[(r0 + g + 8) * SA + cb] = __halves2half2(l0, l1);
        }
        __syncwarp();

        // h2-hi fragments into registers (own rows)
        const uint32_t h2h_addr = sb + O_A1L + a1_off;
        #pragma unroll
        for (int ks = 0; ks < 8; ks++)
            LDSM4(afh[ks], h2h_addr + ks * 32);
    }
    __syncthreads();   // h2h staging / W1 dead; P and B regions free

    // ================= W2 GEMM + spline loop =================
    const uint32_t sbB = sb + O_B;
    float* P = (float*)(smem + O_P);

    // Prefetch B(0) (816 x 16B)
    {
        const char* bsrc = (const char*)g_w2s;
        #pragma unroll
        for (int it = 0; it < 4; it++) {
            int ch = tid + it * 256;
            if (ch < 816) CPASYNC16(sbB + ch * 16, bsrc + ch * 16);
        }
        asm volatile("cp.async.commit_group;" ::: "memory");
    }

    const uint32_t alo_addr = sb + O_A1H + a1_off;
    const uint32_t b_off    = bn1_off;

    float logdet = 0.0f;
    const int myrow = r0 + lane;            // spline row (lane < 16)
    const size_t grow = (size_t)(row0 + myrow);

    for (int j = 0; j < 32; j++) {
        asm volatile("cp.async.wait_group 0;" ::: "memory");
        __syncthreads();   // B(j) visible; P(j-1) reads done block-wide

        if (j + 1 < 32) {
            uint32_t bdst = sbB + ((j + 1) & 1) * BD_BYTES;
            const char* bsrc = (const char*)(g_w2s + (size_t)(j + 1) * BH48H);
            #pragma unroll
            for (int it = 0; it < 4; it++) {
                int ch = tid + it * 256;
                if (ch < 816) CPASYNC16(bdst + ch * 16, bsrc + ch * 16);
            }
        }
        asm volatile("cp.async.commit_group;" ::: "memory");

        // ---- GEMM: 16 rows x 48 cols, 2 terms (h2h*B + h2l*B)
        const uint32_t bh_base = sbB + (j & 1) * BD_BYTES + b_off;

        float acc[6][4];
        #pragma unroll
        for (int t = 0; t < 6; t++)
            #pragma unroll
            for (int q = 0; q < 4; q++) acc[t][q] = 0.0f;

        #pragma unroll
        for (int ks = 0; ks < 8; ks++) {
            uint32_t afl[4];
            LDSM4(afl, alo_addr + ks * 32);
            uint32_t bh[3][4];
            #pragma unroll
            for (int t2 = 0; t2 < 3; t2++) {
                uint32_t o = (uint32_t)(t2 * 16 * SA * 2 + ks * 32);
                LDSM4(bh[t2], bh_base + o);
            }
            #pragma unroll
            for (int t2 = 0; t2 < 3; t2++) {
                mma16816(acc[2 * t2],     afh[ks], bh[t2][0], bh[t2][1]);
                mma16816(acc[2 * t2],     afl,     bh[t2][0], bh[t2][1]);
                mma16816(acc[2 * t2 + 1], afh[ks], bh[t2][2], bh[t2][3]);
                mma16816(acc[2 * t2 + 1], afl,     bh[t2][2], bh[t2][3]);
            }
        }

        // ---- Epilogue: bias, exp for softmax cols (<32)
        const float* bj = &g_b2p[j * 48];
        #pragma unroll
        for (int t = 0; t < 6; t++) {
            int cb = 8 * t + 2 * c2;
            float2 bb = *(const float2*)&bj[cb];
            float v00 = acc[t][0] + bb.x, v01 = acc[t][1] + bb.y;
            float v10 = acc[t][2] + bb.x, v11 = acc[t][3] + bb.y;
            if (t < 4) {
                v00 = __expf(v00); v01 = __expf(v01);
                v10 = __expf(v10); v11 = __expf(v11);
            }
            *(float2*)&P[(r0 + g) * P_STRIDE + cb]     = make_float2(v00, v01);
            *(float2*)&P[(r0 + g + 8) * P_STRIDE + cb] = make_float2(v10, v11);
        }
        __syncwarp();

        // ---- Spline: warp-local, lanes 0..15
        if (lane < 16) {
            const float* pr = &P[myrow * P_STRIDE];
            float tin = __ldg(&x[grow * 64 + j]);

            float sW = 0.0f, sH = 0.0f;
            #pragma unroll
            for (int i = 0; i < 16; i++) { sW += pr[i]; sH += pr[16 + i]; }
            float invW = __fdividef(1.0f, sW);
            float invH = __fdividef(1.0f, sH);

            float tc  = fminf(fmaxf(tin, 0.0f), 1.0f);
            bool  inb = (tin >= 0.0f) && (tin <= 1.0f);

            float xk = 0.0f, cy = 0.0f;
            float xk_b = 0.0f, yk_b = 0.0f;
            float dx_b = pr[0] * invW, dy_b = pr[16] * invH;
            int bidx = 0;
            #pragma unroll
            for (int i = 0; i < 16; i++) {
                float dxi = pr[i] * invW;
                float dyi = pr[16 + i] * invH;
                if (xk <= tc) { bidx = i; xk_b = xk; dx_b = dxi; yk_b = cy; dy_b = dyi; }
                xk += dxi; cy += dyi;
            }

            float v0 = pr[32 + ((bidx > 0) ? bidx - 1 : 0)];
            float v1 = pr[32 + ((bidx < 15) ? bidx : 14)];
            float sp0 = fmaxf(v0, 0.0f) + __logf(1.0f + __expf(-fabsf(v0)));
            float sp1 = fmaxf(v1, 0.0f) + __logf(1.0f + __expf(-fabsf(v1)));
            float d0 = (bidx == 0)  ? 1.0f : sp0;
            float d1 = (bidx == 15) ? 1.0f : sp1;

            float xi   = __fdividef(tc - xk_b, dx_b);
            float s    = __fdividef(dy_b, dx_b);
            float xi1m = xi * (1.0f - xi);
            float den  = s + (d0 + d1 - 2.0f * s) * xi1m;
            float num  = s * xi * xi + d0 * xi1m;
            float y_in = yk_b + dy_b * __fdividef(num, den);
            float omxi = 1.0f - xi;
            float dnum = d1 * xi * xi + 2.0f * s * xi1m + d0 * omxi * omxi;
            float dydx = __fdividef(s * s * dnum, den * den);

            out[grow * 64 + j] = inb ? y_in : tin;
            logdet += inb ? __logf(dydx) : 0.0f;
        }
        __syncwarp();
    }

    if (lane < 16)
        out[(size_t)N * 64 + row0 + myrow] = logdet;
}

// ---------------------------------------------------------------------------
extern "C" void kernel_launch(void* const* d_in, const int* in_sizes, int n_in,
                              void* d_out, int out_size)
{
    const float* x  = (const float*)d_in[0];
    const float* c  = (const float*)d_in[1];
    const float* bs = (const float*)d_in[2];
    const float* bb = (const float*)d_in[3];
    const float* bm = (const float*)d_in[4];
    const float* bv = (const float*)d_in[5];
    const float* W0 = (const float*)d_in[6];
    const float* b0 = (const float*)d_in[7];
    const float* W1 = (const float*)d_in[8];
    const float* b1 = (const float*)d_in[9];
    const float* W2 = (const float*)d_in[10];
    const float* b2 = (const float*)d_in[11];
    float* out = (float*)d_out;

    int N = in_sizes[0] / 64;

    cudaFuncSetAttribute(k_fused, cudaFuncAttributeMaxDynamicSharedMemorySize, (int)SM_TOT);

    k_prep<<<(32 * BH48H + 255) / 256, 256>>>(W0, W1, W2, b2, bs, bb, bm, bv);
    k_fused<<<N / 128, 256, SM_TOT>>>(x, c, b0, b1, out, N);
}

// round 10
// speedup vs baseline: 2.6320x; 1.0072x over previous
#include <cuda_runtime.h>
#include <cuda_fp16.h>
#include <math.h>
#include <stdint.h>

#define SA 136                    // stride (halves) for 128-k tiles
#define S0 56                     // stride (halves) for 48-k tiles
#define P_STRIDE 50
#define BH48H (48 * SA)           // halves per W2 dim tile
#define BD_BYTES (BH48H * 2)      // 13056 bytes per dim

// ---- smem byte offsets (phase-overlaid regions, total 112640) ----
#define O_A1H  0u                 // A1 hi (MLP) -> h2 lo (spline ALo)   34816
#define O_A1L  34816u             // A1 lo -> h2 hi staging -> P         34816
#define O_W1   69632u             // W1 tile (after A0/W0 die)           34816
#define O_A0H  69632u             // A0 hi                               14336
#define O_A0L  83968u             // A0 lo                               14336
#define O_W0   98304u             // W0 tile                             14336
#define O_P    34816u             // P 128 x 50 f32                      25600
#define O_B    60416u             // B ring: 4 stages x 13056 = 52224
#define SM_TOT 112640u

// Pre-converted weights / params (k_prep)
__device__ __half g_w0t[128 * S0];      // W0 n-major [n][k], k<48
__device__ __half g_w1t[128 * SA];      // W1 n-major [n][k], k<128
__device__ __half g_w2s[32 * BH48H];    // W2 tiles per dim, n-major
__device__ float  g_b2p[32 * 48];       // padded b2
__device__ float  g_ab[96];             // BN alpha[48], beta[48]

__device__ __forceinline__ float swishf(float v) {
    return __fdividef(v, 1.0f + __expf(-v));
}

__device__ __forceinline__ void split_fp16(float v, __half* h, __half* l) {
    __half hh = __float2half_rn(v);
    *h = hh;
    *l = __float2half_rn(v - __half2float(hh));
}

__device__ __forceinline__ void mma16816(float* c, const uint32_t* a,
                                         uint32_t b0, uint32_t b1) {
    asm volatile(
        "mma.sync.aligned.m16n8k16.row.col.f32.f16.f16.f32 "
        "{%0,%1,%2,%3}, {%4,%5,%6,%7}, {%8,%9}, {%0,%1,%2,%3};"
        : "+f"(c[0]), "+f"(c[1]), "+f"(c[2]), "+f"(c[3])
        : "r"(a[0]), "r"(a[1]), "r"(a[2]), "r"(a[3]), "r"(b0), "r"(b1));
}

#define LDSM4(d, addr)                                                       \
    asm volatile("ldmatrix.sync.aligned.m8n8.x4.shared.b16 {%0,%1,%2,%3}, [%4];" \
        : "=r"((d)[0]), "=r"((d)[1]), "=r"((d)[2]), "=r"((d)[3]) : "r"(addr))

#define CPASYNC16(dst, src) \
    asm volatile("cp.async.cg.shared.global [%0], [%1], 16;" :: "r"(dst), "l"(src) : "memory")

__device__ __forceinline__ uint32_t smem_u32(const void* p) {
    uint32_t a;
    asm("{ .reg .u64 t; cvta.to.shared.u64 t, %1; cvt.u32.u64 %0, t; }" : "=r"(a) : "l"(p));
    return a;
}

// ---------------------------------------------------------------------------
// Prep: convert all weights to fp16 tiles + BN coefficients + padded bias
// ---------------------------------------------------------------------------
__global__ __launch_bounds__(256)
void k_prep(const float* __restrict__ W0, const float* __restrict__ W1,
            const float* __restrict__ W2, const float* __restrict__ b2,
            const float* __restrict__ bn_scale, const float* __restrict__ bn_bias,
            const float* __restrict__ bn_mean, const float* __restrict__ bn_var)
{
    int idx = blockIdx.x * 256 + threadIdx.x;
    if (idx < 32 * BH48H) {              // W2 tiles
        int j = idx / BH48H;
        int rem = idx - j * BH48H;
        int n = rem / SA;
        int k = rem - n * SA;
        float v = (n < 47 && k < 128) ? W2[(size_t)k * 1504 + j * 47 + n] : 0.0f;
        g_w2s[idx] = __float2half_rn(v);
    }
    if (idx < 128 * SA) {                // W1 tile
        int n = idx / SA, k = idx - n * SA;
        g_w1t[idx] = (k < 128) ? __float2half_rn(W1[(size_t)k * 128 + n]) : __float2half_rn(0.0f);
    }
    if (idx < 128 * S0) {                // W0 tile
        int n = idx / S0, k = idx - n * S0;
        g_w0t[idx] = (k < 48) ? __float2half_rn(W0[(size_t)k * 128 + n]) : __float2half_rn(0.0f);
    }
    if (idx < 32 * 48) {                 // padded b2
        int j = idx / 48, cc = idx - j * 48;
        g_b2p[idx] = (cc < 47) ? b2[j * 47 + cc] : 0.0f;
    }
    if (idx < 48) {                      // BN coefficients
        float a = bn_scale[idx] * rsqrtf(bn_var[idx] + 1e-5f);
        g_ab[idx]      = a;
        g_ab[48 + idx] = bn_bias[idx] - bn_mean[idx] * a;
    }
}

// ---------------------------------------------------------------------------
// Fused kernel: BN + MLP (fp16 HMMA, 2-term A-split) + W2 GEMM + RQS spline.
// Block = 128 rows, 256 threads (8 warps x 16 rows), 2 blocks/SM.
// W2 loop: 4-stage B ring, one __syncthreads per dim-pair placed AFTER
// cp.async.wait_group 0 (per-thread groups -> barrier must follow the wait
// to publish all threads' copies; this was the round-9 race).
// ---------------------------------------------------------------------------
__global__ __launch_bounds__(256, 2)
void k_fused(const float* __restrict__ x, const float* __restrict__ c,
             const float* __restrict__ b0, const float* __restrict__ b1,
             float* __restrict__ out, int N)
{
    extern __shared__ char smem[];
    const uint32_t sb = smem_u32(smem);

    const int tid  = threadIdx.x;
    const int warp = tid >> 5;
    const int lane = tid & 31;
    const int g    = lane >> 2;
    const int c2   = lane & 3;
    const int r0   = warp * 16;
    const int row0 = blockIdx.x * 128;

    // ---- W0 cp.async (896 x 16B)
    {
        const char* src = (const char*)g_w0t;
        #pragma unroll
        for (int it = 0; it < 4; it++) {
            int ch = tid + it * 256;
            if (ch < 896) CPASYNC16(sb + O_W0 + ch * 16, src + ch * 16);
        }
        asm volatile("cp.async.commit_group;" ::: "memory");
    }

    // ---- Stage A0 (BN'd [xc|c]), warp-local rows, fp16 hi/lo; copy xc -> out
    {
        __half* A0h = (__half*)(smem + O_A0H);
        __half* A0l = (__half*)(smem + O_A0L);
        for (int i = lane; i < 16 * 48; i += 32) {
            int r = i / 48, k = i - (i / 48) * 48;
            size_t rg = (size_t)(row0 + r0 + r);
            float v;
            if (k < 32) { v = x[rg * 64 + 32 + k]; out[rg * 64 + 32 + k] = v; }
            else        { v = c[rg * 16 + (k - 32)]; }
            float a = v * g_ab[k] + g_ab[48 + k];
            __half h, l;
            split_fp16(a, &h, &l);
            A0h[(r0 + r) * S0 + k] = h;
            A0l[(r0 + r) * S0 + k] = l;
        }
    }
    asm volatile("cp.async.wait_group 0;" ::: "memory");
    __syncthreads();   // W0 + all A0 rows visible

    // Fragment address components
    const uint32_t a0_off  = (uint32_t)(((r0 + (lane & 15)) * S0 + ((lane >> 4) << 3)) * 2);
    const uint32_t a1_off  = (uint32_t)(((r0 + (lane & 15)) * SA + ((lane >> 4) << 3)) * 2);
    const uint32_t bn0_off = (uint32_t)((((lane & 7) + ((lane >> 4) << 3)) * S0) * 2 + (((lane >> 3) & 1) << 4));
    const uint32_t bn1_off = (uint32_t)((((lane & 7) + ((lane >> 4) << 3)) * SA) * 2 + (((lane >> 3) & 1) << 4));

    // ================= L0: h1 = swish(A0 @ W0 + b0) =====
    {
        float acc[16][4];
        #pragma unroll
        for (int t = 0; t < 16; t++)
            #pragma unroll
            for (int q = 0; q < 4; q++) acc[t][q] = 0.0f;

        const uint32_t a0h_addr = sb + O_A0H + a0_off;
        const uint32_t a0l_addr = sb + O_A0L + a0_off;
        const uint32_t w0_base  = sb + O_W0 + bn0_off;

        #pragma unroll
        for (int ks = 0; ks < 3; ks++) {
            uint32_t ah[4], al[4];
            LDSM4(ah, a0h_addr + ks * 32);
            LDSM4(al, a0l_addr + ks * 32);
            #pragma unroll
            for (int t2 = 0; t2 < 8; t2++) {
                uint32_t bw[4];
                LDSM4(bw, w0_base + t2 * 16 * S0 * 2 + ks * 32);
                mma16816(acc[2 * t2],     ah, bw[0], bw[1]);
                mma16816(acc[2 * t2],     al, bw[0], bw[1]);
                mma16816(acc[2 * t2 + 1], ah, bw[2], bw[3]);
                mma16816(acc[2 * t2 + 1], al, bw[2], bw[3]);
            }
        }

        __half* A1h = (__half*)(smem + O_A1H);
        __half* A1l = (__half*)(smem + O_A1L);
        #pragma unroll
        for (int t = 0; t < 16; t++) {
            int cb = 8 * t + 2 * c2;
            float2 bb = __ldg((const float2*)&b0[cb]);
            float v00 = swishf(acc[t][0] + bb.x), v01 = swishf(acc[t][1] + bb.y);
            float v10 = swishf(acc[t][2] + bb.x), v11 = swishf(acc[t][3] + bb.y);
            __half h0, l0, h1, l1;
            split_fp16(v00, &h0, &l0); split_fp16(v01, &h1, &l1);
            *(__half2*)&A1h[(r0 + g) * SA + cb] = __halves2half2(h0, h1);
            *(__half2*)&A1l[(r0 + g) * SA + cb] = __halves2half2(l0, l1);
            split_fp16(v10, &h0, &l0); split_fp16(v11, &h1, &l1);
            *(__half2*)&A1h[(r0 + g + 8) * SA + cb] = __halves2half2(h0, h1);
            *(__half2*)&A1l[(r0 + g + 8) * SA + cb] = __halves2half2(l0, l1);
        }
    }
    __syncthreads();   // all warps done with A0/W0 region

    // ---- W1 cp.async into (dead) A0/W0 region (2176 x 16B)
    {
        const char* src = (const char*)g_w1t;
        #pragma unroll
        for (int it = 0; it < 9; it++) {
            int ch = tid + it * 256;
            if (ch < 2176) CPASYNC16(sb + O_W1 + ch * 16, src + ch * 16);
        }
        asm volatile("cp.async.commit_group;" ::: "memory");
        asm volatile("cp.async.wait_group 0;" ::: "memory");
    }
    __syncthreads();

    // ================= L1: h2 = swish(A1 @ W1 + b1), K=128 ==================
    uint32_t afh[8][4];    // h2 hi fragments (A of the W2 GEMM)
    {
        float acc[16][4];
        #pragma unroll
        for (int t = 0; t < 16; t++)
            #pragma unroll
            for (int q = 0; q < 4; q++) acc[t][q] = 0.0f;

        const uint32_t a1h_addr = sb + O_A1H + a1_off;
        const uint32_t a1l_addr = sb + O_A1L + a1_off;
        const uint32_t w1_base  = sb + O_W1 + bn1_off;

        #pragma unroll
        for (int ks = 0; ks < 8; ks++) {
            uint32_t ah[4], al[4];
            LDSM4(ah, a1h_addr + ks * 32);
            LDSM4(al, a1l_addr + ks * 32);
            #pragma unroll
            for (int t2 = 0; t2 < 8; t2++) {
                uint32_t bw[4];
                LDSM4(bw, w1_base + t2 * 16 * SA * 2 + ks * 32);
                mma16816(acc[2 * t2],     ah, bw[0], bw[1]);
                mma16816(acc[2 * t2],     al, bw[0], bw[1]);
                mma16816(acc[2 * t2 + 1], ah, bw[2], bw[3]);
                mma16816(acc[2 * t2 + 1], al, bw[2], bw[3]);
            }
        }
        __syncwarp();   // own A1 rows consumed; safe to overwrite (warp-local)

        __half* H2h = (__half*)(smem + O_A1L);
        __half* H2l = (__half*)(smem + O_A1H);
        #pragma unroll
        for (int t = 0; t < 16; t++) {
            int cb = 8 * t + 2 * c2;
            float2 bb = __ldg((const float2*)&b1[cb]);
            float v00 = swishf(acc[t][0] + bb.x), v01 = swishf(acc[t][1] + bb.y);
            float v10 = swishf(acc[t][2] + bb.x), v11 = swishf(acc[t][3] + bb.y);
            __half h0, l0, h1, l1;
            split_fp16(v00, &h0, &l0); split_fp16(v01, &h1, &l1);
            *(__half2*)&H2h[(r0 + g) * SA + cb] = __halves2half2(h0, h1);
            *(__half2*)&H2l[(r0 + g) * SA + cb] = __halves2half2(l0, l1);
            split_fp16(v10, &h0, &l0); split_fp16(v11, &h1, &l1);
            *(__half2*)&H2h[(r0 + g + 8) * SA + cb] = __halves2half2(h0, h1);
            *(__half2*)&H2l[(r0 + g + 8) * SA + cb] = __halves2half2(l0, l1);
        }
        __syncwarp();

        const uint32_t h2h_addr = sb + O_A1L + a1_off;
        #pragma unroll
        for (int ks = 0; ks < 8; ks++)
            LDSM4(afh[ks], h2h_addr + ks * 32);
    }
    __syncthreads();   // h2h staging / W1 dead; P and B regions free

    // ================= W2 GEMM + spline loop (4-stage B ring) =================
    const uint32_t sbB = sb + O_B;
    float* P = (float*)(smem + O_P);

    // Prologue: prefetch pair 0 (dims 0,1) as one group
    {
        #pragma unroll
        for (int dd = 0; dd < 2; dd++) {
            uint32_t bdst = sbB + (uint32_t)dd * BD_BYTES;
            const char* bsrc = (const char*)(g_w2s + (size_t)dd * BH48H);
            #pragma unroll
            for (int it = 0; it < 4; it++) {
                int ch = tid + it * 256;
                if (ch < 816) CPASYNC16(bdst + ch * 16, bsrc + ch * 16);
            }
        }
        asm volatile("cp.async.commit_group;" ::: "memory");
    }

    const uint32_t alo_addr = sb + O_A1H + a1_off;
    const uint32_t b_off    = bn1_off;

    float logdet = 0.0f;
    const int myrow = r0 + lane;            // spline row (lane < 16)
    const size_t grow = (size_t)(row0 + myrow);

    for (int jp = 0; jp < 16; jp++) {
        // Own copies of pair jp done (committed a full pair ago)...
        asm volatile("cp.async.wait_group 0;" ::: "memory");
        // ...then barrier publishes ALL threads' copies, and retires pair
        // jp-1 reads before its slots are overwritten below.
        __syncthreads();

        if (jp < 15) {
            // Prefetch pair jp+1 (dims 2jp+2, 2jp+3) into their ring slots
            #pragma unroll
            for (int dd = 0; dd < 2; dd++) {
                int dim = 2 * jp + 2 + dd;
                uint32_t bdst = sbB + (uint32_t)(dim & 3) * BD_BYTES;
                const char* bsrc = (const char*)(g_w2s + (size_t)dim * BH48H);
                #pragma unroll
                for (int it = 0; it < 4; it++) {
                    int ch = tid + it * 256;
                    if (ch < 816) CPASYNC16(bdst + ch * 16, bsrc + ch * 16);
                }
            }
            asm volatile("cp.async.commit_group;" ::: "memory");
        }

        // ---- Two dims, warp-local only (warps drift within the pair)
        #pragma unroll
        for (int dd = 0; dd < 2; dd++) {
            const int j = 2 * jp + dd;
            const uint32_t bh_base = sbB + (uint32_t)(j & 3) * BD_BYTES + b_off;

            float acc[6][4];
            #pragma unroll
            for (int t = 0; t < 6; t++)
                #pragma unroll
                for (int q = 0; q < 4; q++) acc[t][q] = 0.0f;

            #pragma unroll
            for (int ks = 0; ks < 8; ks++) {
                uint32_t afl[4];
                LDSM4(afl, alo_addr + ks * 32);
                uint32_t bh[3][4];
                #pragma unroll
                for (int t2 = 0; t2 < 3; t2++) {
                    uint32_t o = (uint32_t)(t2 * 16 * SA * 2 + ks * 32);
                    LDSM4(bh[t2], bh_base + o);
                }
                #pragma unroll
                for (int t2 = 0; t2 < 3; t2++) {
                    mma16816(acc[2 * t2],     afh[ks], bh[t2][0], bh[t2][1]);
                    mma16816(acc[2 * t2],     afl,     bh[t2][0], bh[t2][1]);
                    mma16816(acc[2 * t2 + 1], afh[ks], bh[t2][2], bh[t2][3]);
                    mma16816(acc[2 * t2 + 1], afl,     bh[t2][2], bh[t2][3]);
                }
            }

            // ---- Epilogue: bias, exp for softmax cols (<32)
            const float* bj = &g_b2p[j * 48];
            #pragma unroll
            for (int t = 0; t < 6; t++) {
                int cb = 8 * t + 2 * c2;
                float2 bb = *(const float2*)&bj[cb];
                float v00 = acc[t][0] + bb.x, v01 = acc[t][1] + bb.y;
                float v10 = acc[t][2] + bb.x, v11 = acc[t][3] + bb.y;
                if (t < 4) {
                    v00 = __expf(v00); v01 = __expf(v01);
                    v10 = __expf(v10); v11 = __expf(v11);
                }
                *(float2*)&P[(r0 + g) * P_STRIDE + cb]     = make_float2(v00, v01);
                *(float2*)&P[(r0 + g + 8) * P_STRIDE + cb] = make_float2(v10, v11);
            }
            __syncwarp();

            // ---- Spline: warp-local, lanes 0..15
            if (lane < 16) {
                const float* pr = &P[myrow * P_STRIDE];
                float tin = __ldg(&x[grow * 64 + j]);

                float sW = 0.0f, sH = 0.0f;
                #pragma unroll
                for (int i = 0; i < 16; i++) { sW += pr[i]; sH += pr[16 + i]; }
                float invW = __fdividef(1.0f, sW);
                float invH = __fdividef(1.0f, sH);

                float tc  = fminf(fmaxf(tin, 0.0f), 1.0f);
                bool  inb = (tin >= 0.0f) && (tin <= 1.0f);

                float xk = 0.0f, cy = 0.0f;
                float xk_b = 0.0f, yk_b = 0.0f;
                float dx_b = pr[0] * invW, dy_b = pr[16] * invH;
                int bidx = 0;
                #pragma unroll
                for (int i = 0; i < 16; i++) {
                    float dxi = pr[i] * invW;
                    float dyi = pr[16 + i] * invH;
                    if (xk <= tc) { bidx = i; xk_b = xk; dx_b = dxi; yk_b = cy; dy_b = dyi; }
                    xk += dxi; cy += dyi;
                }

                float v0 = pr[32 + ((bidx > 0) ? bidx - 1 : 0)];
                float v1 = pr[32 + ((bidx < 15) ? bidx : 14)];
                float sp0 = fmaxf(v0, 0.0f) + __logf(1.0f + __expf(-fabsf(v0)));
                float sp1 = fmaxf(v1, 0.0f) + __logf(1.0f + __expf(-fabsf(v1)));
                float d0 = (bidx == 0)  ? 1.0f : sp0;
                float d1 = (bidx == 15) ? 1.0f : sp1;

                float xi   = __fdividef(tc - xk_b, dx_b);
                float s    = __fdividef(dy_b, dx_b);
                float xi1m = xi * (1.0f - xi);
                float den  = s + (d0 + d1 - 2.0f * s) * xi1m;
                float num  = s * xi * xi + d0 * xi1m;
                float y_in = yk_b + dy_b * __fdividef(num, den);
                float omxi = 1.0f - xi;
                float dnum = d1 * xi * xi + 2.0f * s * xi1m + d0 * omxi * omxi;
                float dydx = __fdividef(s * s * dnum, den * den);

                out[grow * 64 + j] = inb ? y_in : tin;
                logdet += inb ? __logf(dydx) : 0.0f;
            }
            __syncwarp();
        }
    }

    if (lane < 16)
        out[(size_t)N * 64 + row0 + myrow] = logdet;
}

// ---------------------------------------------------------------------------
extern "C" void kernel_launch(void* const* d_in, const int* in_sizes, int n_in,
                              void* d_out, int out_size)
{
    const float* x  = (const float*)d_in[0];
    const float* c  = (const float*)d_in[1];
    const float* bs = (const float*)d_in[2];
    const float* bb = (const float*)d_in[3];
    const float* bm = (const float*)d_in[4];
    const float* bv = (const float*)d_in[5];
    const float* W0 = (const float*)d_in[6];
    const float* b0 = (const float*)d_in[7];
    const float* W1 = (const float*)d_in[8];
    const float* b1 = (const float*)d_in[9];
    const float* W2 = (const float*)d_in[10];
    const float* b2 = (const float*)d_in[11];
    float* out = (float*)d_out;

    int N = in_sizes[0] / 64;

    cudaFuncSetAttribute(k_fused, cudaFuncAttributeMaxDynamicSharedMemorySize, (int)SM_TOT);

    k_prep<<<(32 * BH48H + 255) / 256, 256>>>(W0, W1, W2, b2, bs, bb, bm, bv);
    k_fused<<<N / 128, 256, SM_TOT>>>(x, c, b0, b1, out, N);
}

// round 11
// speedup vs baseline: 3.4827x; 1.3232x over previous
#include <cuda_runtime.h>
#include <cuda_fp16.h>
#include <math.h>
#include <stdint.h>

#define SA 136                    // stride (halves) for 128-k tiles
#define S0 56                     // stride (halves) for 48-k tiles
#define PW 100                    // P stride (floats); dim1 at +50
#define BH48H (48 * SA)           // halves per W2 dim tile
#define BD_BYTES (BH48H * 2)      // 13056 bytes per dim

// ---- smem byte offsets ----
// MLP phase:   A1H 0..34816 | A1L 34816..69632 (-> h2-hi staging) | W1 69632..104448
//              (A0H/A0L/W0 live inside 69632..112640 before W1)
// Spline phase: P 0..51200 (128 x 100 f32) | B ring 60416..112640 (4 x 13056)
#define O_A1H  0u
#define O_A1L  34816u
#define O_W1   69632u
#define O_A0H  69632u
#define O_A0L  83968u
#define O_W0   98304u
#define O_P    0u
#define O_B    60416u
#define SM_TOT 112640u

// Pre-converted weights / params (k_prep)
__device__ __half g_w0t[128 * S0];      // W0 n-major [n][k], k<48
__device__ __half g_w1t[128 * SA];      // W1 n-major [n][k], k<128
__device__ __half g_w2s[32 * BH48H];    // W2 tiles per dim, n-major
__device__ float  g_b2p[32 * 48];       // padded b2
__device__ float  g_ab[96];             // BN alpha[48], beta[48]

__device__ __forceinline__ float swishf(float v) {
    return __fdividef(v, 1.0f + __expf(-v));
}

__device__ __forceinline__ void split_fp16(float v, __half* h, __half* l) {
    __half hh = __float2half_rn(v);
    *h = hh;
    *l = __float2half_rn(v - __half2float(hh));
}

__device__ __forceinline__ void mma16816(float* c, const uint32_t* a,
                                         uint32_t b0, uint32_t b1) {
    asm volatile(
        "mma.sync.aligned.m16n8k16.row.col.f32.f16.f16.f32 "
        "{%0,%1,%2,%3}, {%4,%5,%6,%7}, {%8,%9}, {%0,%1,%2,%3};"
        : "+f"(c[0]), "+f"(c[1]), "+f"(c[2]), "+f"(c[3])
        : "r"(a[0]), "r"(a[1]), "r"(a[2]), "r"(a[3]), "r"(b0), "r"(b1));
}

#define LDSM4(d, addr)                                                       \
    asm volatile("ldmatrix.sync.aligned.m8n8.x4.shared.b16 {%0,%1,%2,%3}, [%4];" \
        : "=r"((d)[0]), "=r"((d)[1]), "=r"((d)[2]), "=r"((d)[3]) : "r"(addr))

#define CPASYNC16(dst, src) \
    asm volatile("cp.async.cg.shared.global [%0], [%1], 16;" :: "r"(dst), "l"(src) : "memory")

__device__ __forceinline__ uint32_t smem_u32(const void* p) {
    uint32_t a;
    asm("{ .reg .u64 t; cvta.to.shared.u64 t, %1; cvt.u32.u64 %0, t; }" : "=r"(a) : "l"(p));
    return a;
}

// ---------------------------------------------------------------------------
// Prep: convert all weights to fp16 tiles + BN coefficients + padded bias
// ---------------------------------------------------------------------------
__global__ __launch_bounds__(256)
void k_prep(const float* __restrict__ W0, const float* __restrict__ W1,
            const float* __restrict__ W2, const float* __restrict__ b2,
            const float* __restrict__ bn_scale, const float* __restrict__ bn_bias,
            const float* __restrict__ bn_mean, const float* __restrict__ bn_var)
{
    int idx = blockIdx.x * 256 + threadIdx.x;
    if (idx < 32 * BH48H) {              // W2 tiles
        int j = idx / BH48H;
        int rem = idx - j * BH48H;
        int n = rem / SA;
        int k = rem - n * SA;
        float v = (n < 47 && k < 128) ? W2[(size_t)k * 1504 + j * 47 + n] : 0.0f;
        g_w2s[idx] = __float2half_rn(v);
    }
    if (idx < 128 * SA) {                // W1 tile
        int n = idx / SA, k = idx - n * SA;
        g_w1t[idx] = (k < 128) ? __float2half_rn(W1[(size_t)k * 128 + n]) : __float2half_rn(0.0f);
    }
    if (idx < 128 * S0) {                // W0 tile
        int n = idx / S0, k = idx - n * S0;
        g_w0t[idx] = (k < 48) ? __float2half_rn(W0[(size_t)k * 128 + n]) : __float2half_rn(0.0f);
    }
    if (idx < 32 * 48) {                 // padded b2
        int j = idx / 48, cc = idx - j * 48;
        g_b2p[idx] = (cc < 47) ? b2[j * 47 + cc] : 0.0f;
    }
    if (idx < 48) {                      // BN coefficients
        float a = bn_scale[idx] * rsqrtf(bn_var[idx] + 1e-5f);
        g_ab[idx]      = a;
        g_ab[48 + idx] = bn_bias[idx] - bn_mean[idx] * a;
    }
}

// ---------------------------------------------------------------------------
// Fused kernel: BN + MLP (fp16 HMMA, 2-term A-split) + W2 GEMM (single-term,
// h2-hi only) + dual-dim 32-lane RQS spline.
// Block = 128 rows, 256 threads (8 warps x 16 rows), 2 blocks/SM.
// ---------------------------------------------------------------------------
__global__ __launch_bounds__(256, 2)
void k_fused(const float* __restrict__ x, const float* __restrict__ c,
             const float* __restrict__ b0, const float* __restrict__ b1,
             float* __restrict__ out, int N)
{
    extern __shared__ char smem[];
    const uint32_t sb = smem_u32(smem);

    const int tid  = threadIdx.x;
    const int warp = tid >> 5;
    const int lane = tid & 31;
    const int g    = lane >> 2;
    const int c2   = lane & 3;
    const int r0   = warp * 16;
    const int row0 = blockIdx.x * 128;

    // ---- W0 cp.async (896 x 16B)
    {
        const char* src = (const char*)g_w0t;
        #pragma unroll
        for (int it = 0; it < 4; it++) {
            int ch = tid + it * 256;
            if (ch < 896) CPASYNC16(sb + O_W0 + ch * 16, src + ch * 16);
        }
        asm volatile("cp.async.commit_group;" ::: "memory");
    }

    // ---- Stage A0 (BN'd [xc|c]), warp-local rows, fp16 hi/lo; copy xc -> out
    {
        __half* A0h = (__half*)(smem + O_A0H);
        __half* A0l = (__half*)(smem + O_A0L);
        for (int i = lane; i < 16 * 48; i += 32) {
            int r = i / 48, k = i - (i / 48) * 48;
            size_t rg = (size_t)(row0 + r0 + r);
            float v;
            if (k < 32) { v = x[rg * 64 + 32 + k]; out[rg * 64 + 32 + k] = v; }
            else        { v = c[rg * 16 + (k - 32)]; }
            float a = v * g_ab[k] + g_ab[48 + k];
            __half h, l;
            split_fp16(a, &h, &l);
            A0h[(r0 + r) * S0 + k] = h;
            A0l[(r0 + r) * S0 + k] = l;
        }
    }
    asm volatile("cp.async.wait_group 0;" ::: "memory");
    __syncthreads();   // W0 + all A0 rows visible

    // Fragment address components
    const uint32_t a0_off  = (uint32_t)(((r0 + (lane & 15)) * S0 + ((lane >> 4) << 3)) * 2);
    const uint32_t a1_off  = (uint32_t)(((r0 + (lane & 15)) * SA + ((lane >> 4) << 3)) * 2);
    const uint32_t bn0_off = (uint32_t)((((lane & 7) + ((lane >> 4) << 3)) * S0) * 2 + (((lane >> 3) & 1) << 4));
    const uint32_t bn1_off = (uint32_t)((((lane & 7) + ((lane >> 4) << 3)) * SA) * 2 + (((lane >> 3) & 1) << 4));

    // ================= L0: h1 = swish(A0 @ W0 + b0) =====
    {
        float acc[16][4];
        #pragma unroll
        for (int t = 0; t < 16; t++)
            #pragma unroll
            for (int q = 0; q < 4; q++) acc[t][q] = 0.0f;

        const uint32_t a0h_addr = sb + O_A0H + a0_off;
        const uint32_t a0l_addr = sb + O_A0L + a0_off;
        const uint32_t w0_base  = sb + O_W0 + bn0_off;

        #pragma unroll
        for (int ks = 0; ks < 3; ks++) {
            uint32_t ah[4], al[4];
            LDSM4(ah, a0h_addr + ks * 32);
            LDSM4(al, a0l_addr + ks * 32);
            #pragma unroll
            for (int t2 = 0; t2 < 8; t2++) {
                uint32_t bw[4];
                LDSM4(bw, w0_base + t2 * 16 * S0 * 2 + ks * 32);
                mma16816(acc[2 * t2],     ah, bw[0], bw[1]);
                mma16816(acc[2 * t2],     al, bw[0], bw[1]);
                mma16816(acc[2 * t2 + 1], ah, bw[2], bw[3]);
                mma16816(acc[2 * t2 + 1], al, bw[2], bw[3]);
            }
        }

        __half* A1h = (__half*)(smem + O_A1H);
        __half* A1l = (__half*)(smem + O_A1L);
        #pragma unroll
        for (int t = 0; t < 16; t++) {
            int cb = 8 * t + 2 * c2;
            float2 bb = __ldg((const float2*)&b0[cb]);
            float v00 = swishf(acc[t][0] + bb.x), v01 = swishf(acc[t][1] + bb.y);
            float v10 = swishf(acc[t][2] + bb.x), v11 = swishf(acc[t][3] + bb.y);
            __half h0, l0, h1, l1;
            split_fp16(v00, &h0, &l0); split_fp16(v01, &h1, &l1);
            *(__half2*)&A1h[(r0 + g) * SA + cb] = __halves2half2(h0, h1);
            *(__half2*)&A1l[(r0 + g) * SA + cb] = __halves2half2(l0, l1);
            split_fp16(v10, &h0, &l0); split_fp16(v11, &h1, &l1);
            *(__half2*)&A1h[(r0 + g + 8) * SA + cb] = __halves2half2(h0, h1);
            *(__half2*)&A1l[(r0 + g + 8) * SA + cb] = __halves2half2(l0, l1);
        }
    }
    __syncthreads();   // all warps done with A0/W0 region

    // ---- W1 cp.async into (dead) A0/W0 region (2176 x 16B)
    {
        const char* src = (const char*)g_w1t;
        #pragma unroll
        for (int it = 0; it < 9; it++) {
            int ch = tid + it * 256;
            if (ch < 2176) CPASYNC16(sb + O_W1 + ch * 16, src + ch * 16);
        }
        asm volatile("cp.async.commit_group;" ::: "memory");
        asm volatile("cp.async.wait_group 0;" ::: "memory");
    }
    __syncthreads();

    // ================= L1: h2 = swish(A1 @ W1 + b1), K=128 ==================
    uint32_t afh[8][4];    // h2-hi fragments (sole A operand of the W2 GEMM)
    {
        float acc[16][4];
        #pragma unroll
        for (int t = 0; t < 16; t++)
            #pragma unroll
            for (int q = 0; q < 4; q++) acc[t][q] = 0.0f;

        const uint32_t a1h_addr = sb + O_A1H + a1_off;
        const uint32_t a1l_addr = sb + O_A1L + a1_off;
        const uint32_t w1_base  = sb + O_W1 + bn1_off;

        #pragma unroll
        for (int ks = 0; ks < 8; ks++) {
            uint32_t ah[4], al[4];
            LDSM4(ah, a1h_addr + ks * 32);
            LDSM4(al, a1l_addr + ks * 32);
            #pragma unroll
            for (int t2 = 0; t2 < 8; t2++) {
                uint32_t bw[4];
                LDSM4(bw, w1_base + t2 * 16 * SA * 2 + ks * 32);
                mma16816(acc[2 * t2],     ah, bw[0], bw[1]);
                mma16816(acc[2 * t2],     al, bw[0], bw[1]);
                mma16816(acc[2 * t2 + 1], ah, bw[2], bw[3]);
                mma16816(acc[2 * t2 + 1], al, bw[2], bw[3]);
            }
        }
        __syncwarp();   // own A1 rows consumed; safe to overwrite (warp-local)

        // Epilogue: h2-hi only -> staging in O_A1L region
        __half* H2h = (__half*)(smem + O_A1L);
        #pragma unroll
        for (int t = 0; t < 16; t++) {
            int cb = 8 * t + 2 * c2;
            float2 bb = __ldg((const float2*)&b1[cb]);
            float v00 = swishf(acc[t][0] + bb.x), v01 = swishf(acc[t][1] + bb.y);
            float v10 = swishf(acc[t][2] + bb.x), v11 = swishf(acc[t][3] + bb.y);
            *(__half2*)&H2h[(r0 + g) * SA + cb] =
                __halves2half2(__float2half_rn(v00), __float2half_rn(v01));
            *(__half2*)&H2h[(r0 + g + 8) * SA + cb] =
                __halves2half2(__float2half_rn(v10), __float2half_rn(v11));
        }
        __syncwarp();

        const uint32_t h2h_addr = sb + O_A1L + a1_off;
        #pragma unroll
        for (int ks = 0; ks < 8; ks++)
            LDSM4(afh[ks], h2h_addr + ks * 32);
    }
    __syncthreads();   // staging / W1 dead; P and B regions free

    // ================= W2 GEMM + dual-dim spline loop (4-stage B ring) ======
    const uint32_t sbB = sb + O_B;
    float* P = (float*)(smem + O_P);

    // Prologue: prefetch pair 0 (dims 0,1) as one group
    {
        #pragma unroll
        for (int dd = 0; dd < 2; dd++) {
            uint32_t bdst = sbB + (uint32_t)dd * BD_BYTES;
            const char* bsrc = (const char*)(g_w2s + (size_t)dd * BH48H);
            #pragma unroll
            for (int it = 0; it < 4; it++) {
                int ch = tid + it * 256;
                if (ch < 816) CPASYNC16(bdst + ch * 16, bsrc + ch * 16);
            }
        }
        asm volatile("cp.async.commit_group;" ::: "memory");
    }

    const uint32_t b_off = bn1_off;
    const int jj = lane >> 4;               // 0: dim j0, 1: dim j1 (spline half)
    const int myrow = r0 + (lane & 15);
    const size_t grow = (size_t)(row0 + myrow);

    float logdet = 0.0f;

    for (int jp = 0; jp < 16; jp++) {
        // Own copies of pair jp done, then publish all threads' copies and
        // retire pair jp-1 reads before its slots are overwritten.
        asm volatile("cp.async.wait_group 0;" ::: "memory");
        __syncthreads();

        if (jp < 15) {
            #pragma unroll
            for (int dd = 0; dd < 2; dd++) {
                int dim = 2 * jp + 2 + dd;
                uint32_t bdst = sbB + (uint32_t)(dim & 3) * BD_BYTES;
                const char* bsrc = (const char*)(g_w2s + (size_t)dim * BH48H);
                #pragma unroll
                for (int it = 0; it < 4; it++) {
                    int ch = tid + it * 256;
                    if (ch < 816) CPASYNC16(bdst + ch * 16, bsrc + ch * 16);
                }
            }
            asm volatile("cp.async.commit_group;" ::: "memory");
        }

        // ---- Two GEMMs + epilogues (single-term: h2-hi x B)
        #pragma unroll
        for (int dd = 0; dd < 2; dd++) {
            const int j = 2 * jp + dd;
            const uint32_t bh_base = sbB + (uint32_t)(j & 3) * BD_BYTES + b_off;

            float acc[6][4];
            #pragma unroll
            for (int t = 0; t < 6; t++)
                #pragma unroll
                for (int q = 0; q < 4; q++) acc[t][q] = 0.0f;

            #pragma unroll
            for (int ks = 0; ks < 8; ks++) {
                uint32_t bh[3][4];
                #pragma unroll
                for (int t2 = 0; t2 < 3; t2++) {
                    uint32_t o = (uint32_t)(t2 * 16 * SA * 2 + ks * 32);
                    LDSM4(bh[t2], bh_base + o);
                }
                #pragma unroll
                for (int t2 = 0; t2 < 3; t2++) {
                    mma16816(acc[2 * t2],     afh[ks], bh[t2][0], bh[t2][1]);
                    mma16816(acc[2 * t2 + 1], afh[ks], bh[t2][2], bh[t2][3]);
                }
            }

            // Epilogue: bias, exp for softmax cols (<32); dim dd at +50 cols
            const float* bj = &g_b2p[j * 48];
            const int co = dd * 50;
            #pragma unroll
            for (int t = 0; t < 6; t++) {
                int cb = 8 * t + 2 * c2;
                float2 bb = *(const float2*)&bj[cb];
                float v00 = acc[t][0] + bb.x, v01 = acc[t][1] + bb.y;
                float v10 = acc[t][2] + bb.x, v11 = acc[t][3] + bb.y;
                if (t < 4) {
                    v00 = __expf(v00); v01 = __expf(v01);
                    v10 = __expf(v10); v11 = __expf(v11);
                }
                *(float2*)&P[(r0 + g) * PW + co + cb]     = make_float2(v00, v01);
                *(float2*)&P[(r0 + g + 8) * PW + co + cb] = make_float2(v10, v11);
            }
        }
        __syncwarp();

        // ---- Spline: ALL 32 lanes (lanes 0-15: dim j0; 16-31: dim j1)
        {
            const int j = 2 * jp + jj;
            const float* pr = &P[myrow * PW + jj * 50];
            float tin = __ldg(&x[grow * 64 + j]);

            float sW = 0.0f, sH = 0.0f;
            #pragma unroll
            for (int i = 0; i < 16; i++) { sW += pr[i]; sH += pr[16 + i]; }
            float invW = __fdividef(1.0f, sW);
            float invH = __fdividef(1.0f, sH);

            float tc  = fminf(fmaxf(tin, 0.0f), 1.0f);
            bool  inb = (tin >= 0.0f) && (tin <= 1.0f);

            float xk = 0.0f, cy = 0.0f;
            float xk_b = 0.0f, yk_b = 0.0f;
            float dx_b = pr[0] * invW, dy_b = pr[16] * invH;
            int bidx = 0;
            #pragma unroll
            for (int i = 0; i < 16; i++) {
                float dxi = pr[i] * invW;
                float dyi = pr[16 + i] * invH;
                if (xk <= tc) { bidx = i; xk_b = xk; dx_b = dxi; yk_b = cy; dy_b = dyi; }
                xk += dxi; cy += dyi;
            }

            float v0 = pr[32 + ((bidx > 0) ? bidx - 1 : 0)];
            float v1 = pr[32 + ((bidx < 15) ? bidx : 14)];
            float sp0 = fmaxf(v0, 0.0f) + __logf(1.0f + __expf(-fabsf(v0)));
            float sp1 = fmaxf(v1, 0.0f) + __logf(1.0f + __expf(-fabsf(v1)));
            float d0 = (bidx == 0)  ? 1.0f : sp0;
            float d1 = (bidx == 15) ? 1.0f : sp1;

            float xi   = __fdividef(tc - xk_b, dx_b);
            float s    = __fdividef(dy_b, dx_b);
            float xi1m = xi * (1.0f - xi);
            float den  = s + (d0 + d1 - 2.0f * s) * xi1m;
            float num  = s * xi * xi + d0 * xi1m;
            float y_in = yk_b + dy_b * __fdividef(num, den);
            float omxi = 1.0f - xi;
            float dnum = d1 * xi * xi + 2.0f * s * xi1m + d0 * omxi * omxi;
            float dydx = __fdividef(s * s * dnum, den * den);

            out[grow * 64 + j] = inb ? y_in : tin;
            logdet += inb ? __logf(dydx) : 0.0f;
        }
        __syncwarp();   // P reads retired before next pair's epilogue writes
    }

    // Combine the two half-warp logdet partials (even dims in lanes 0-15,
    // odd dims in lanes 16-31) and store.
    logdet += __shfl_down_sync(0xffffffffu, logdet, 16);
    if (lane < 16)
        out[(size_t)N * 64 + row0 + myrow] = logdet;
}

// ---------------------------------------------------------------------------
extern "C" void kernel_launch(void* const* d_in, const int* in_sizes, int n_in,
                              void* d_out, int out_size)
{
    const float* x  = (const float*)d_in[0];
    const float* c  = (const float*)d_in[1];
    const float* bs = (const float*)d_in[2];
    const float* bb = (const float*)d_in[3];
    const float* bm = (const float*)d_in[4];
    const float* bv = (const float*)d_in[5];
    const float* W0 = (const float*)d_in[6];
    const float* b0 = (const float*)d_in[7];
    const float* W1 = (const float*)d_in[8];
    const float* b1 = (const float*)d_in[9];
    const float* W2 = (const float*)d_in[10];
    const float* b2 = (const float*)d_in[11];
    float* out = (float*)d_out;

    int N = in_sizes[0] / 64;

    cudaFuncSetAttribute(k_fused, cudaFuncAttributeMaxDynamicSharedMemorySize, (int)SM_TOT);

    k_prep<<<(32 * BH48H + 255) / 256, 256>>>(W0, W1, W2, b2, bs, bb, bm, bv);
    k_fused<<<N / 128, 256, SM_TOT>>>(x, c, b0, b1, out, N);
}

// round 12
// speedup vs baseline: 3.5813x; 1.0283x over previous
#include <cuda_runtime.h>
#include <cuda_fp16.h>
#include <math.h>
#include <stdint.h>

#define SA 136                    // stride (halves) for 128-k tiles
#define S0 56                     // stride (halves) for 48-k tiles
#define PW 100                    // P stride (floats); dim1 at +50
#define BH48H (48 * SA)           // halves per W2 dim tile
#define BD_BYTES (BH48H * 2)      // 13056 bytes per dim

// ---- smem byte offsets ----
#define O_A1H  0u
#define O_A1L  34816u
#define O_W1   69632u
#define O_A0H  69632u
#define O_A0L  83968u
#define O_W0   98304u
#define O_P    0u
#define O_B    60416u
#define SM_TOT 112640u

// Pre-converted weights / params (k_prep)
__device__ __half g_w0t[128 * S0];      // W0 n-major [n][k], k<48
__device__ __half g_w1t[128 * SA];      // W1 n-major [n][k], k<128
__device__ __half g_w2s[32 * BH48H];    // W2 tiles per dim, n-major
__device__ float  g_b2p[32 * 48];       // padded b2
__device__ float  g_ab[96];             // BN alpha[48], beta[48]

__device__ __forceinline__ float swishf(float v) {
    return __fdividef(v, 1.0f + __expf(-v));
}

__device__ __forceinline__ void split_fp16(float v, __half* h, __half* l) {
    __half hh = __float2half_rn(v);
    *h = hh;
    *l = __float2half_rn(v - __half2float(hh));
}

__device__ __forceinline__ void mma16816(float* c, const uint32_t* a,
                                         uint32_t b0, uint32_t b1) {
    asm volatile(
        "mma.sync.aligned.m16n8k16.row.col.f32.f16.f16.f32 "
        "{%0,%1,%2,%3}, {%4,%5,%6,%7}, {%8,%9}, {%0,%1,%2,%3};"
        : "+f"(c[0]), "+f"(c[1]), "+f"(c[2]), "+f"(c[3])
        : "r"(a[0]), "r"(a[1]), "r"(a[2]), "r"(a[3]), "r"(b0), "r"(b1));
}

#define LDSM4(d, addr)                                                       \
    asm volatile("ldmatrix.sync.aligned.m8n8.x4.shared.b16 {%0,%1,%2,%3}, [%4];" \
        : "=r"((d)[0]), "=r"((d)[1]), "=r"((d)[2]), "=r"((d)[3]) : "r"(addr))

#define CPASYNC16(dst, src) \
    asm volatile("cp.async.cg.shared.global [%0], [%1], 16;" :: "r"(dst), "l"(src) : "memory")

__device__ __forceinline__ uint32_t smem_u32(const void* p) {
    uint32_t a;
    asm("{ .reg .u64 t; cvta.to.shared.u64 t, %1; cvt.u32.u64 %0, t; }" : "=r"(a) : "l"(p));
    return a;
}

// ---------------------------------------------------------------------------
// Spline for one pair (all 32 lanes: 0-15 -> dim 2jp, 16-31 -> dim 2jp+1).
// Reads P (warp-private rows), writes y to out, returns logdet increment.
// ---------------------------------------------------------------------------
__device__ __forceinline__ float spline_pair(const float* __restrict__ P,
                                             const float* __restrict__ x,
                                             float* __restrict__ out,
                                             int jp, int jj, int myrow,
                                             size_t grow)
{
    const int j = 2 * jp + jj;
    const float* pr = &P[myrow * PW + jj * 50];
    float tin = __ldg(&x[grow * 64 + j]);

    float sW = 0.0f, sH = 0.0f;
    #pragma unroll
    for (int i = 0; i < 16; i++) { sW += pr[i]; sH += pr[16 + i]; }
    float invW = __fdividef(1.0f, sW);
    float invH = __fdividef(1.0f, sH);

    float tc  = fminf(fmaxf(tin, 0.0f), 1.0f);
    bool  inb = (tin >= 0.0f) && (tin <= 1.0f);

    float xk = 0.0f, cy = 0.0f;
    float xk_b = 0.0f, yk_b = 0.0f;
    float dx_b = pr[0] * invW, dy_b = pr[16] * invH;
    int bidx = 0;
    #pragma unroll
    for (int i = 0; i < 16; i++) {
        float dxi = pr[i] * invW;
        float dyi = pr[16 + i] * invH;
        if (xk <= tc) { bidx = i; xk_b = xk; dx_b = dxi; yk_b = cy; dy_b = dyi; }
        xk += dxi; cy += dyi;
    }

    float v0 = pr[32 + ((bidx > 0) ? bidx - 1 : 0)];
    float v1 = pr[32 + ((bidx < 15) ? bidx : 14)];
    float sp0 = fmaxf(v0, 0.0f) + __logf(1.0f + __expf(-fabsf(v0)));
    float sp1 = fmaxf(v1, 0.0f) + __logf(1.0f + __expf(-fabsf(v1)));
    float d0 = (bidx == 0)  ? 1.0f : sp0;
    float d1 = (bidx == 15) ? 1.0f : sp1;

    float xi   = __fdividef(tc - xk_b, dx_b);
    float s    = __fdividef(dy_b, dx_b);
    float xi1m = xi * (1.0f - xi);
    float den  = s + (d0 + d1 - 2.0f * s) * xi1m;
    float num  = s * xi * xi + d0 * xi1m;
    float y_in = yk_b + dy_b * __fdividef(num, den);
    float omxi = 1.0f - xi;
    float dnum = d1 * xi * xi + 2.0f * s * xi1m + d0 * omxi * omxi;
    float dydx = __fdividef(s * s * dnum, den * den);

    out[grow * 64 + j] = inb ? y_in : tin;
    return inb ? __logf(dydx) : 0.0f;
}

// ---------------------------------------------------------------------------
// Prep: convert all weights to fp16 tiles + BN coefficients + padded bias
// ---------------------------------------------------------------------------
__global__ __launch_bounds__(256)
void k_prep(const float* __restrict__ W0, const float* __restrict__ W1,
            const float* __restrict__ W2, const float* __restrict__ b2,
            const float* __restrict__ bn_scale, const float* __restrict__ bn_bias,
            const float* __restrict__ bn_mean, const float* __restrict__ bn_var)
{
    int idx = blockIdx.x * 256 + threadIdx.x;
    if (idx < 32 * BH48H) {              // W2 tiles
        int j = idx / BH48H;
        int rem = idx - j * BH48H;
        int n = rem / SA;
        int k = rem - n * SA;
        float v = (n < 47 && k < 128) ? W2[(size_t)k * 1504 + j * 47 + n] : 0.0f;
        g_w2s[idx] = __float2half_rn(v);
    }
    if (idx < 128 * SA) {                // W1 tile
        int n = idx / SA, k = idx - n * SA;
        g_w1t[idx] = (k < 128) ? __float2half_rn(W1[(size_t)k * 128 + n]) : __float2half_rn(0.0f);
    }
    if (idx < 128 * S0) {                // W0 tile
        int n = idx / S0, k = idx - n * S0;
        g_w0t[idx] = (k < 48) ? __float2half_rn(W0[(size_t)k * 128 + n]) : __float2half_rn(0.0f);
    }
    if (idx < 32 * 48) {                 // padded b2
        int j = idx / 48, cc = idx - j * 48;
        g_b2p[idx] = (cc < 47) ? b2[j * 47 + cc] : 0.0f;
    }
    if (idx < 48) {                      // BN coefficients
        float a = bn_scale[idx] * rsqrtf(bn_var[idx] + 1e-5f);
        g_ab[idx]      = a;
        g_ab[48 + idx] = bn_bias[idx] - bn_mean[idx] * a;
    }
}

// ---------------------------------------------------------------------------
// Fused kernel: BN + MLP (fp16 HMMA, 2-term A-split) + W2 GEMM (single-term)
// + software-pipelined dual-dim spline (spline(jp-1) under GEMM(jp) MMAs).
// Block = 128 rows, 256 threads (8 warps x 16 rows), 2 blocks/SM.
// ---------------------------------------------------------------------------
__global__ __launch_bounds__(256, 2)
void k_fused(const float* __restrict__ x, const float* __restrict__ c,
             const float* __restrict__ b0, const float* __restrict__ b1,
             float* __restrict__ out, int N)
{
    extern __shared__ char smem[];
    const uint32_t sb = smem_u32(smem);

    const int tid  = threadIdx.x;
    const int warp = tid >> 5;
    const int lane = tid & 31;
    const int g    = lane >> 2;
    const int c2   = lane & 3;
    const int r0   = warp * 16;
    const int row0 = blockIdx.x * 128;

    // ---- W0 cp.async (896 x 16B)
    {
        const char* src = (const char*)g_w0t;
        #pragma unroll
        for (int it = 0; it < 4; it++) {
            int ch = tid + it * 256;
            if (ch < 896) CPASYNC16(sb + O_W0 + ch * 16, src + ch * 16);
        }
        asm volatile("cp.async.commit_group;" ::: "memory");
    }

    // ---- Stage A0 (BN'd [xc|c]), warp-local rows, fp16 hi/lo; copy xc -> out
    {
        __half* A0h = (__half*)(smem + O_A0H);
        __half* A0l = (__half*)(smem + O_A0L);
        for (int i = lane; i < 16 * 48; i += 32) {
            int r = i / 48, k = i - (i / 48) * 48;
            size_t rg = (size_t)(row0 + r0 + r);
            float v;
            if (k < 32) { v = x[rg * 64 + 32 + k]; out[rg * 64 + 32 + k] = v; }
            else        { v = c[rg * 16 + (k - 32)]; }
            float a = v * g_ab[k] + g_ab[48 + k];
            __half h, l;
            split_fp16(a, &h, &l);
            A0h[(r0 + r) * S0 + k] = h;
            A0l[(r0 + r) * S0 + k] = l;
        }
    }
    asm volatile("cp.async.wait_group 0;" ::: "memory");
    __syncthreads();   // W0 + all A0 rows visible

    // Fragment address components
    const uint32_t a0_off  = (uint32_t)(((r0 + (lane & 15)) * S0 + ((lane >> 4) << 3)) * 2);
    const uint32_t a1_off  = (uint32_t)(((r0 + (lane & 15)) * SA + ((lane >> 4) << 3)) * 2);
    const uint32_t bn0_off = (uint32_t)((((lane & 7) + ((lane >> 4) << 3)) * S0) * 2 + (((lane >> 3) & 1) << 4));
    const uint32_t bn1_off = (uint32_t)((((lane & 7) + ((lane >> 4) << 3)) * SA) * 2 + (((lane >> 3) & 1) << 4));

    // ================= L0: h1 = swish(A0 @ W0 + b0) =====
    {
        float acc[16][4];
        #pragma unroll
        for (int t = 0; t < 16; t++)
            #pragma unroll
            for (int q = 0; q < 4; q++) acc[t][q] = 0.0f;

        const uint32_t a0h_addr = sb + O_A0H + a0_off;
        const uint32_t a0l_addr = sb + O_A0L + a0_off;
        const uint32_t w0_base  = sb + O_W0 + bn0_off;

        #pragma unroll
        for (int ks = 0; ks < 3; ks++) {
            uint32_t ah[4], al[4];
            LDSM4(ah, a0h_addr + ks * 32);
            LDSM4(al, a0l_addr + ks * 32);
            #pragma unroll
            for (int t2 = 0; t2 < 8; t2++) {
                uint32_t bw[4];
                LDSM4(bw, w0_base + t2 * 16 * S0 * 2 + ks * 32);
                mma16816(acc[2 * t2],     ah, bw[0], bw[1]);
                mma16816(acc[2 * t2],     al, bw[0], bw[1]);
                mma16816(acc[2 * t2 + 1], ah, bw[2], bw[3]);
                mma16816(acc[2 * t2 + 1], al, bw[2], bw[3]);
            }
        }

        __half* A1h = (__half*)(smem + O_A1H);
        __half* A1l = (__half*)(smem + O_A1L);
        #pragma unroll
        for (int t = 0; t < 16; t++) {
            int cb = 8 * t + 2 * c2;
            float2 bb = __ldg((const float2*)&b0[cb]);
            float v00 = swishf(acc[t][0] + bb.x), v01 = swishf(acc[t][1] + bb.y);
            float v10 = swishf(acc[t][2] + bb.x), v11 = swishf(acc[t][3] + bb.y);
            __half h0, l0, h1, l1;
            split_fp16(v00, &h0, &l0); split_fp16(v01, &h1, &l1);
            *(__half2*)&A1h[(r0 + g) * SA + cb] = __halves2half2(h0, h1);
            *(__half2*)&A1l[(r0 + g) * SA + cb] = __halves2half2(l0, l1);
            split_fp16(v10, &h0, &l0); split_fp16(v11, &h1, &l1);
            *(__half2*)&A1h[(r0 + g + 8) * SA + cb] = __halves2half2(h0, h1);
            *(__half2*)&A1l[(r0 + g + 8) * SA + cb] = __halves2half2(l0, l1);
        }
    }
    __syncthreads();   // all warps done with A0/W0 region

    // ---- W1 cp.async into (dead) A0/W0 region (2176 x 16B)
    {
        const char* src = (const char*)g_w1t;
        #pragma unroll
        for (int it = 0; it < 9; it++) {
            int ch = tid + it * 256;
            if (ch < 2176) CPASYNC16(sb + O_W1 + ch * 16, src + ch * 16);
        }
        asm volatile("cp.async.commit_group;" ::: "memory");
        asm volatile("cp.async.wait_group 0;" ::: "memory");
    }
    __syncthreads();

    // ================= L1: h2 = swish(A1 @ W1 + b1), K=128 ==================
    uint32_t afh[8][4];    // h2-hi fragments (sole A operand of the W2 GEMM)
    {
        float acc[16][4];
        #pragma unroll
        for (int t = 0; t < 16; t++)
            #pragma unroll
            for (int q = 0; q < 4; q++) acc[t][q] = 0.0f;

        const uint32_t a1h_addr = sb + O_A1H + a1_off;
        const uint32_t a1l_addr = sb + O_A1L + a1_off;
        const uint32_t w1_base  = sb + O_W1 + bn1_off;

        #pragma unroll
        for (int ks = 0; ks < 8; ks++) {
            uint32_t ah[4], al[4];
            LDSM4(ah, a1h_addr + ks * 32);
            LDSM4(al, a1l_addr + ks * 32);
            #pragma unroll
            for (int t2 = 0; t2 < 8; t2++) {
                uint32_t bw[4];
                LDSM4(bw, w1_base + t2 * 16 * SA * 2 + ks * 32);
                mma16816(acc[2 * t2],     ah, bw[0], bw[1]);
                mma16816(acc[2 * t2],     al, bw[0], bw[1]);
                mma16816(acc[2 * t2 + 1], ah, bw[2], bw[3]);
                mma16816(acc[2 * t2 + 1], al, bw[2], bw[3]);
            }
        }
        __syncwarp();   // own A1 rows consumed; safe to overwrite (warp-local)

        // Epilogue: h2-hi only -> staging in O_A1L region
        __half* H2h = (__half*)(smem + O_A1L);
        #pragma unroll
        for (int t = 0; t < 16; t++) {
            int cb = 8 * t + 2 * c2;
            float2 bb = __ldg((const float2*)&b1[cb]);
            float v00 = swishf(acc[t][0] + bb.x), v01 = swishf(acc[t][1] + bb.y);
            float v10 = swishf(acc[t][2] + bb.x), v11 = swishf(acc[t][3] + bb.y);
            *(__half2*)&H2h[(r0 + g) * SA + cb] =
                __halves2half2(__float2half_rn(v00), __float2half_rn(v01));
            *(__half2*)&H2h[(r0 + g + 8) * SA + cb] =
                __halves2half2(__float2half_rn(v10), __float2half_rn(v11));
        }
        __syncwarp();

        const uint32_t h2h_addr = sb + O_A1L + a1_off;
        #pragma unroll
        for (int ks = 0; ks < 8; ks++)
            LDSM4(afh[ks], h2h_addr + ks * 32);
    }
    __syncthreads();   // staging / W1 dead; P and B regions free

    // ================= W2 GEMM + software-pipelined spline ==================
    const uint32_t sbB = sb + O_B;
    float* P = (float*)(smem + O_P);

    // Prologue: prefetch pair 0 (dims 0,1) as one group
    {
        #pragma unroll
        for (int dd = 0; dd < 2; dd++) {
            uint32_t bdst = sbB + (uint32_t)dd * BD_BYTES;
            const char* bsrc = (const char*)(g_w2s + (size_t)dd * BH48H);
            #pragma unroll
            for (int it = 0; it < 4; it++) {
                int ch = tid + it * 256;
                if (ch < 816) CPASYNC16(bdst + ch * 16, bsrc + ch * 16);
            }
        }
        asm volatile("cp.async.commit_group;" ::: "memory");
    }

    const uint32_t b_off = bn1_off;
    const int jj = lane >> 4;               // 0: dim j0, 1: dim j1 (spline half)
    const int myrow = r0 + (lane & 15);
    const size_t grow = (size_t)(row0 + myrow);

    float logdet = 0.0f;

    for (int jp = 0; jp < 16; jp++) {
        // Own copies of pair jp done, then publish all threads' copies and
        // retire pair jp-1 GEMM reads before its slots are overwritten.
        asm volatile("cp.async.wait_group 0;" ::: "memory");
        __syncthreads();

        if (jp < 15) {
            #pragma unroll
            for (int dd = 0; dd < 2; dd++) {
                int dim = 2 * jp + 2 + dd;
                uint32_t bdst = sbB + (uint32_t)(dim & 3) * BD_BYTES;
                const char* bsrc = (const char*)(g_w2s + (size_t)dim * BH48H);
                #pragma unroll
                for (int it = 0; it < 4; it++) {
                    int ch = tid + it * 256;
                    if (ch < 816) CPASYNC16(bdst + ch * 16, bsrc + ch * 16);
                }
            }
            asm volatile("cp.async.commit_group;" ::: "memory");
        }

        // ---- GEMM dim j0 (issue MMAs; results needed only at epilogue)
        const int j0 = 2 * jp;
        float acc0[6][4];
        #pragma unroll
        for (int t = 0; t < 6; t++)
            #pragma unroll
            for (int q = 0; q < 4; q++) acc0[t][q] = 0.0f;
        {
            const uint32_t bh_base = sbB + (uint32_t)(j0 & 3) * BD_BYTES + b_off;
            #pragma unroll
            for (int ks = 0; ks < 8; ks++) {
                uint32_t bh[3][4];
                #pragma unroll
                for (int t2 = 0; t2 < 3; t2++) {
                    uint32_t o = (uint32_t)(t2 * 16 * SA * 2 + ks * 32);
                    LDSM4(bh[t2], bh_base + o);
                }
                #pragma unroll
                for (int t2 = 0; t2 < 3; t2++) {
                    mma16816(acc0[2 * t2],     afh[ks], bh[t2][0], bh[t2][1]);
                    mma16816(acc0[2 * t2 + 1], afh[ks], bh[t2][2], bh[t2][3]);
                }
            }
        }

        // ---- Spline for the PREVIOUS pair, overlapping j0's in-flight MMAs
        if (jp > 0)
            logdet += spline_pair(P, x, out, jp - 1, jj, myrow, grow);
        __syncwarp();   // P(jp-1) reads retired before epilogues overwrite P

        // ---- GEMM dim j1
        const int j1 = 2 * jp + 1;
        float acc1[6][4];
        #pragma unroll
        for (int t = 0; t < 6; t++)
            #pragma unroll
            for (int q = 0; q < 4; q++) acc1[t][q] = 0.0f;
        {
            const uint32_t bh_base = sbB + (uint32_t)(j1 & 3) * BD_BYTES + b_off;
            #pragma unroll
            for (int ks = 0; ks < 8; ks++) {
                uint32_t bh[3][4];
                #pragma unroll
                for (int t2 = 0; t2 < 3; t2++) {
                    uint32_t o = (uint32_t)(t2 * 16 * SA * 2 + ks * 32);
                    LDSM4(bh[t2], bh_base + o);
                }
                #pragma unroll
                for (int t2 = 0; t2 < 3; t2++) {
                    mma16816(acc1[2 * t2],     afh[ks], bh[t2][0], bh[t2][1]);
                    mma16816(acc1[2 * t2 + 1], afh[ks], bh[t2][2], bh[t2][3]);
                }
            }
        }

        // ---- Epilogues (bias, exp for softmax cols) -> P halves
        {
            const float* bj = &g_b2p[j0 * 48];
            #pragma unroll
            for (int t = 0; t < 6; t++) {
                int cb = 8 * t + 2 * c2;
                float2 bb = *(const float2*)&bj[cb];
                float v00 = acc0[t][0] + bb.x, v01 = acc0[t][1] + bb.y;
                float v10 = acc0[t][2] + bb.x, v11 = acc0[t][3] + bb.y;
                if (t < 4) {
                    v00 = __expf(v00); v01 = __expf(v01);
                    v10 = __expf(v10); v11 = __expf(v11);
                }
                *(float2*)&P[(r0 + g) * PW + cb]     = make_float2(v00, v01);
                *(float2*)&P[(r0 + g + 8) * PW + cb] = make_float2(v10, v11);
            }
        }
        {
            const float* bj = &g_b2p[j1 * 48];
            #pragma unroll
            for (int t = 0; t < 6; t++) {
                int cb = 8 * t + 2 * c2;
                float2 bb = *(const float2*)&bj[cb];
                float v00 = acc1[t][0] + bb.x, v01 = acc1[t][1] + bb.y;
                float v10 = acc1[t][2] + bb.x, v11 = acc1[t][3] + bb.y;
                if (t < 4) {
                    v00 = __expf(v00); v01 = __expf(v01);
                    v10 = __expf(v10); v11 = __expf(v11);
                }
                *(float2*)&P[(r0 + g) * PW + 50 + cb]     = make_float2(v00, v01);
                *(float2*)&P[(r0 + g + 8) * PW + 50 + cb] = make_float2(v10, v11);
            }
        }
        __syncwarp();   // P(jp) visible to spline next iteration
    }

    // Drain: spline for the last pair
    logdet += spline_pair(P, x, out, 15, jj, myrow, grow);

    // Combine the two half-warp logdet partials and store.
    logdet += __shfl_down_sync(0xffffffffu, logdet, 16);
    if (lane < 16)
        out[(size_t)N * 64 + row0 + myrow] = logdet;
}

// ---------------------------------------------------------------------------
extern "C" void kernel_launch(void* const* d_in, const int* in_sizes, int n_in,
                              void* d_out, int out_size)
{
    const float* x  = (const float*)d_in[0];
    const float* c  = (const float*)d_in[1];
    const float* bs = (const float*)d_in[2];
    const float* bb = (const float*)d_in[3];
    const float* bm = (const float*)d_in[4];
    const float* bv = (const float*)d_in[5];
    const float* W0 = (const float*)d_in[6];
    const float* b0 = (const float*)d_in[7];
    const float* W1 = (const float*)d_in[8];
    const float* b1 = (const float*)d_in[9];
    const float* W2 = (const float*)d_in[10];
    const float* b2 = (const float*)d_in[11];
    float* out = (float*)d_out;

    int N = in_sizes[0] / 64;

    cudaFuncSetAttribute(k_fused, cudaFuncAttributeMaxDynamicSharedMemorySize, (int)SM_TOT);

    k_prep<<<(32 * BH48H + 255) / 256, 256>>>(W0, W1, W2, b2, bs, bb, bm, bv);
    k_fused<<<N / 128, 256, SM_TOT>>>(x, c, b0, b1, out, N);
}